// round 1
// baseline (speedup 1.0000x reference)
#include <cuda_runtime.h>
#include <cuda_bf16.h>
#include <math.h>

// Problem constants
#define S_   1024
#define H_   2880
#define NH_  64
#define NKV_ 8
#define HD_  64
#define QKV_N_ 5120              // (NH + 2*NKV) * HD
#define QOFF_  0
#define KOFF_  4096              // NH*HD
#define VOFF_  4608              // NH*HD + NKV*HD
#define ATTN_N_ 4096             // NH*HD
#define SCALE_ 0.125f            // HD^-0.5
#define QT_ 4                    // queries per attention block

// Scratch (allocation-free: __device__ globals)
__device__ float g_qkv[S_ * QKV_N_];    // 20 MB: qkv = hidden @ qkv_w^T (rope applied in place)
__device__ float g_attn[S_ * ATTN_N_];  // 16 MB: attention output, pre-O-proj

// ---------------------------------------------------------------------------
// SGEMM (NT): C[m,n] = sum_k A[m*K+k] * B[n*K+k]
// A: [M,K] row-major, B: [N,K] row-major (weights), C: [M,N] row-major.
// BM=128, BN=64, BK=16, 256 threads, each thread computes 8x4.
// ---------------------------------------------------------------------------
#define BM 128
#define BN 64
#define BK 16

__global__ __launch_bounds__(256)
void sgemm_nt(const float* __restrict__ A, const float* __restrict__ B,
              float* __restrict__ C, int M, int N, int K)
{
    __shared__ float As[BK][BM];
    __shared__ float Bs[BK][BN];

    const int tid = threadIdx.x;
    const int bm = blockIdx.y * BM;
    const int bn = blockIdx.x * BN;
    const int tx = tid & 15;        // 0..15 -> N
    const int ty = tid >> 4;        // 0..15 -> M

    // load mapping: 4 float4 per 16-float row
    const int arow = tid >> 2;        // 0..63
    const int acol = (tid & 3) * 4;   // 0,4,8,12

    float acc[8][4];
#pragma unroll
    for (int i = 0; i < 8; i++)
#pragma unroll
        for (int j = 0; j < 4; j++) acc[i][j] = 0.f;

    for (int k0 = 0; k0 < K; k0 += BK) {
        float4 a0 = *(const float4*)&A[(size_t)(bm + arow)      * K + k0 + acol];
        float4 a1 = *(const float4*)&A[(size_t)(bm + arow + 64) * K + k0 + acol];
        float4 b0 = *(const float4*)&B[(size_t)(bn + arow)      * K + k0 + acol];

        As[acol + 0][arow] = a0.x;  As[acol + 1][arow] = a0.y;
        As[acol + 2][arow] = a0.z;  As[acol + 3][arow] = a0.w;
        As[acol + 0][arow + 64] = a1.x;  As[acol + 1][arow + 64] = a1.y;
        As[acol + 2][arow + 64] = a1.z;  As[acol + 3][arow + 64] = a1.w;
        Bs[acol + 0][arow] = b0.x;  Bs[acol + 1][arow] = b0.y;
        Bs[acol + 2][arow] = b0.z;  Bs[acol + 3][arow] = b0.w;
        __syncthreads();

#pragma unroll
        for (int k = 0; k < BK; k++) {
            float4 av0 = *(const float4*)&As[k][ty * 8];
            float4 av1 = *(const float4*)&As[k][ty * 8 + 4];
            float4 bv  = *(const float4*)&Bs[k][tx * 4];
            float a[8] = {av0.x, av0.y, av0.z, av0.w, av1.x, av1.y, av1.z, av1.w};
            float b[4] = {bv.x, bv.y, bv.z, bv.w};
#pragma unroll
            for (int i = 0; i < 8; i++)
#pragma unroll
                for (int j = 0; j < 4; j++)
                    acc[i][j] = fmaf(a[i], b[j], acc[i][j]);
        }
        __syncthreads();
    }

#pragma unroll
    for (int i = 0; i < 8; i++) {
        float4 o = make_float4(acc[i][0], acc[i][1], acc[i][2], acc[i][3]);
        *(float4*)&C[(size_t)(bm + ty * 8 + i) * N + bn + tx * 4] = o;
    }
}

// ---------------------------------------------------------------------------
// RoPE in-place on q and k rows of g_qkv. One 32-thread block per (s, head).
// ---------------------------------------------------------------------------
__global__ void rope_kernel(const int* __restrict__ positions)
{
    const int row = blockIdx.x;          // 0 .. S*(NH+NKV)-1
    const int s  = row / (NH_ + NKV_);
    const int hh = row % (NH_ + NKV_);
    float* base = (hh < NH_)
        ? &g_qkv[(size_t)s * QKV_N_ + hh * HD_]
        : &g_qkv[(size_t)s * QKV_N_ + KOFF_ + (hh - NH_) * HD_];

    const int i = threadIdx.x;           // 0..31
    const float pos = (float)positions[s];
    const float inv_freq = powf(10000.0f, -(float)i / 32.0f);
    const float ang = pos * inv_freq;
    float c, sn;
    sincosf(ang, &sn, &c);
    const float x1 = base[i];
    const float x2 = base[i + 32];
    base[i]      = x1 * c - x2 * sn;
    base[i + 32] = x2 * c + x1 * sn;
}

// ---------------------------------------------------------------------------
// GQA causal attention with sinks.
// Grid: (S/QT, NH). Block: 128 threads. 4 queries per block, K/V rows reused.
// ---------------------------------------------------------------------------
__global__ __launch_bounds__(128)
void attn_kernel(const float* __restrict__ sinks)
{
    __shared__ float q_s[QT_][HD_];
    __shared__ float sc[QT_][S_];        // 16 KB scores -> probabilities
    __shared__ float red[QT_ * 128];
    __shared__ float m_s[QT_], den_s[QT_];

    const int h   = blockIdx.y;
    const int q0  = blockIdx.x * QT_;
    const int kv  = h >> 3;              // h / G, G = 8
    const int tid = threadIdx.x;
    const float sink = sinks[h];
    const int kmax = q0 + QT_ - 1;

    // load the 4 query rows (rope already applied)
    for (int i = tid; i < QT_ * HD_; i += 128) {
        int iq = i >> 6, d = i & 63;
        q_s[iq][d] = g_qkv[(size_t)(q0 + iq) * QKV_N_ + h * HD_ + d];
    }
    __syncthreads();

    // Phase 1: scores + local max
    float lmax[QT_];
#pragma unroll
    for (int iq = 0; iq < QT_; iq++) lmax[iq] = -INFINITY;

    for (int k = tid; k <= kmax; k += 128) {
        const float4* K4 = (const float4*)&g_qkv[(size_t)k * QKV_N_ + KOFF_ + kv * HD_];
        float dot[QT_] = {0.f, 0.f, 0.f, 0.f};
#pragma unroll
        for (int c = 0; c < 16; c++) {
            float4 kvv = K4[c];
#pragma unroll
            for (int iq = 0; iq < QT_; iq++) {
                float4 qv = *(const float4*)&q_s[iq][c * 4];
                dot[iq] += qv.x * kvv.x + qv.y * kvv.y + qv.z * kvv.z + qv.w * kvv.w;
            }
        }
#pragma unroll
        for (int iq = 0; iq < QT_; iq++) {
            float s = dot[iq] * SCALE_;
            if (k > q0 + iq) s = -INFINITY;   // causal
            sc[iq][k] = s;
            lmax[iq] = fmaxf(lmax[iq], s);
        }
    }
#pragma unroll
    for (int iq = 0; iq < QT_; iq++) red[iq * 128 + tid] = lmax[iq];
    __syncthreads();
    if (tid < QT_) {
        float m = sink;
        for (int t = 0; t < 128; t++) m = fmaxf(m, red[tid * 128 + t]);
        m_s[tid] = m;
    }
    __syncthreads();

    // Phase 2: exp + sum
    float lsum[QT_] = {0.f, 0.f, 0.f, 0.f};
    for (int k = tid; k <= kmax; k += 128) {
#pragma unroll
        for (int iq = 0; iq < QT_; iq++) {
            float s = sc[iq][k];
            float p = (s == -INFINITY) ? 0.f : __expf(s - m_s[iq]);
            sc[iq][k] = p;
            lsum[iq] += p;
        }
    }
#pragma unroll
    for (int iq = 0; iq < QT_; iq++) red[iq * 128 + tid] = lsum[iq];
    __syncthreads();
    if (tid < QT_) {
        float sum = 0.f;
        for (int t = 0; t < 128; t++) sum += red[tid * 128 + t];
        den_s[tid] = sum + __expf(sink - m_s[tid]);
    }
    __syncthreads();

    // Phase 3: P @ V (split keys across two half-warsets; d = tid & 63)
    const int d = tid & 63;
    const int half = tid >> 6;
    float acc[QT_] = {0.f, 0.f, 0.f, 0.f};
    for (int k = half; k <= kmax; k += 2) {
        float v = g_qkv[(size_t)k * QKV_N_ + VOFF_ + kv * HD_ + d];
#pragma unroll
        for (int iq = 0; iq < QT_; iq++) acc[iq] += sc[iq][k] * v;
    }
    __syncthreads();
#pragma unroll
    for (int iq = 0; iq < QT_; iq++) red[iq * 128 + tid] = acc[iq];
    __syncthreads();
    if (tid < 64) {
#pragma unroll
        for (int iq = 0; iq < QT_; iq++) {
            float o = (red[iq * 128 + tid] + red[iq * 128 + tid + 64]) / den_s[iq];
            g_attn[(size_t)(q0 + iq) * ATTN_N_ + h * HD_ + d] = o;
        }
    }
}

// ---------------------------------------------------------------------------
// Launch
// ---------------------------------------------------------------------------
extern "C" void kernel_launch(void* const* d_in, const int* in_sizes, int n_in,
                              void* d_out, int out_size)
{
    const int*   positions = (const int*)d_in[0];
    const float* hidden    = (const float*)d_in[1];
    const float* qkv_w     = (const float*)d_in[2];
    const float* o_w       = (const float*)d_in[3];
    const float* sinks     = (const float*)d_in[4];
    float*       out       = (float*)d_out;

    void* p_qkv_v;  cudaGetSymbolAddress(&p_qkv_v,  g_qkv);
    void* p_attn_v; cudaGetSymbolAddress(&p_attn_v, g_attn);
    float* p_qkv  = (float*)p_qkv_v;
    float* p_attn = (float*)p_attn_v;

    // 1) QKV projection: [1024,2880] @ [5120,2880]^T -> [1024,5120]
    sgemm_nt<<<dim3(QKV_N_ / BN, S_ / BM), 256>>>(hidden, qkv_w, p_qkv, S_, QKV_N_, H_);

    // 2) RoPE in place on q and k
    rope_kernel<<<S_ * (NH_ + NKV_), 32>>>(positions);

    // 3) Attention
    attn_kernel<<<dim3(S_ / QT_, NH_), 128>>>(sinks);

    // 4) O projection: [1024,4096] @ [2880,4096]^T -> [1024,2880]
    sgemm_nt<<<dim3(H_ / BN, S_ / BM), 256>>>(p_attn, o_w, out, S_, H_, ATTN_N_);
}

// round 2
// speedup vs baseline: 1.0648x; 1.0648x over previous
#include <cuda_runtime.h>
#include <cuda_bf16.h>
#include <math.h>
#include <stdint.h>

// Problem constants
#define S_   1024
#define H_   2880
#define NH_  64
#define NKV_ 8
#define HD_  64
#define QKV_N_ 5120              // (NH + 2*NKV) * HD
#define KOFF_  4096              // NH*HD
#define VOFF_  4608              // NH*HD + NKV*HD
#define ATTN_N_ 4096             // NH*HD
#define SCALE_ 0.125f            // HD^-0.5
#define QT_ 8                    // queries per attention block

// Scratch (allocation-free: __device__ globals)
__device__ float g_qkv[S_ * QKV_N_];    // 20 MB
__device__ float g_attn[S_ * ATTN_N_];  // 16 MB

// ---------------------------------------------------------------------------
// Tensor-core GEMM (NT) with bf16 hi/lo split (3-pass), fp32 accumulate.
// C[m,n] = sum_k A[m,k] * B[n,k].  A:[M,K], B:[N,K] row-major, C:[M,N].
// BM=128, BN=64, BK=32, 256 threads (8 warps: 4 in M x 2 in N, warp tile 32x32)
// ---------------------------------------------------------------------------
#define BM 128
#define BN 64
#define BK 32
#define RSTRIDE 20   // smem row stride in 32-bit words (16 data + 4 pad) -> conflict-free frags

__device__ __forceinline__ void mma16816(float* c, const uint32_t* a, const uint32_t* b) {
    asm volatile(
        "mma.sync.aligned.m16n8k16.row.col.f32.bf16.bf16.f32 "
        "{%0,%1,%2,%3}, {%4,%5,%6,%7}, {%8,%9}, {%0,%1,%2,%3};\n"
        : "+f"(c[0]), "+f"(c[1]), "+f"(c[2]), "+f"(c[3])
        : "r"(a[0]), "r"(a[1]), "r"(a[2]), "r"(a[3]), "r"(b[0]), "r"(b[1]));
}

__device__ __forceinline__ void split2(float x, float y, uint32_t& hi, uint32_t& lo) {
    __nv_bfloat16 hx = __float2bfloat16(x);
    __nv_bfloat16 hy = __float2bfloat16(y);
    __nv_bfloat16 lx = __float2bfloat16(x - __bfloat162float(hx));
    __nv_bfloat16 ly = __float2bfloat16(y - __bfloat162float(hy));
    hi = ((uint32_t)__bfloat16_as_ushort(hy) << 16) | (uint32_t)__bfloat16_as_ushort(hx);
    lo = ((uint32_t)__bfloat16_as_ushort(ly) << 16) | (uint32_t)__bfloat16_as_ushort(lx);
}

__global__ __launch_bounds__(256)
void gemm_bf16x3_nt(const float* __restrict__ A, const float* __restrict__ B,
                    float* __restrict__ C, int M, int N, int K)
{
    __shared__ uint32_t As[2][BM * RSTRIDE];   // [hi/lo][row*RSTRIDE + kword]
    __shared__ uint32_t Bs[2][BN * RSTRIDE];

    const int tid  = threadIdx.x;
    const int wid  = tid >> 5;
    const int lane = tid & 31;
    const int g    = lane >> 2;        // 0..7
    const int cq   = lane & 3;         // 0..3
    const int wm   = (wid & 3) * 32;   // warp M origin in tile
    const int wn   = (wid >> 2) * 32;  // warp N origin in tile
    const int bm   = blockIdx.y * BM;
    const int bn   = blockIdx.x * BN;

    // loaders
    const int a_row = tid >> 1;            // 0..127
    const int a_k   = (tid & 1) * 16;      // 0 / 16
    const int b_row = tid >> 2;            // 0..63
    const int b_k   = (tid & 3) * 8;       // 0,8,16,24

    float acc[2][4][4];
#pragma unroll
    for (int mt = 0; mt < 2; mt++)
#pragma unroll
        for (int nt = 0; nt < 4; nt++)
#pragma unroll
            for (int i = 0; i < 4; i++) acc[mt][nt][i] = 0.f;

    for (int k0 = 0; k0 < K; k0 += BK) {
        // stage A (128x32 fp32 -> hi/lo bf16 pairs)
        {
            const float* ap = &A[(size_t)(bm + a_row) * K + k0 + a_k];
            uint32_t* ah = &As[0][a_row * RSTRIDE + (a_k >> 1)];
            uint32_t* al = &As[1][a_row * RSTRIDE + (a_k >> 1)];
#pragma unroll
            for (int j = 0; j < 16; j += 4) {
                float4 v = *(const float4*)&ap[j];
                uint32_t h0, l0, h1, l1;
                split2(v.x, v.y, h0, l0);
                split2(v.z, v.w, h1, l1);
                ah[(j >> 1) + 0] = h0;  ah[(j >> 1) + 1] = h1;
                al[(j >> 1) + 0] = l0;  al[(j >> 1) + 1] = l1;
            }
        }
        // stage B (64x32)
        {
            const float* bp = &B[(size_t)(bn + b_row) * K + k0 + b_k];
            uint32_t* bh = &Bs[0][b_row * RSTRIDE + (b_k >> 1)];
            uint32_t* bl = &Bs[1][b_row * RSTRIDE + (b_k >> 1)];
#pragma unroll
            for (int j = 0; j < 8; j += 4) {
                float4 v = *(const float4*)&bp[j];
                uint32_t h0, l0, h1, l1;
                split2(v.x, v.y, h0, l0);
                split2(v.z, v.w, h1, l1);
                bh[(j >> 1) + 0] = h0;  bh[(j >> 1) + 1] = h1;
                bl[(j >> 1) + 0] = l0;  bl[(j >> 1) + 1] = l1;
            }
        }
        __syncthreads();

#pragma unroll
        for (int kk = 0; kk < 2; kk++) {
            const int w0 = kk * 8 + cq;
            uint32_t ah[2][4], al[2][4], bh[4][2], bl[4][2];
#pragma unroll
            for (int mt = 0; mt < 2; mt++) {
                int r0 = (wm + mt * 16 + g) * RSTRIDE;
                int r8 = r0 + 8 * RSTRIDE;
                ah[mt][0] = As[0][r0 + w0];
                ah[mt][1] = As[0][r8 + w0];
                ah[mt][2] = As[0][r0 + w0 + 4];
                ah[mt][3] = As[0][r8 + w0 + 4];
                al[mt][0] = As[1][r0 + w0];
                al[mt][1] = As[1][r8 + w0];
                al[mt][2] = As[1][r0 + w0 + 4];
                al[mt][3] = As[1][r8 + w0 + 4];
            }
#pragma unroll
            for (int nt = 0; nt < 4; nt++) {
                int r0 = (wn + nt * 8 + g) * RSTRIDE;
                bh[nt][0] = Bs[0][r0 + w0];
                bh[nt][1] = Bs[0][r0 + w0 + 4];
                bl[nt][0] = Bs[1][r0 + w0];
                bl[nt][1] = Bs[1][r0 + w0 + 4];
            }
#pragma unroll
            for (int mt = 0; mt < 2; mt++)
#pragma unroll
                for (int nt = 0; nt < 4; nt++) {
                    mma16816(acc[mt][nt], ah[mt], bh[nt]);
                    mma16816(acc[mt][nt], ah[mt], bl[nt]);
                    mma16816(acc[mt][nt], al[mt], bh[nt]);
                }
        }
        __syncthreads();
    }

    // epilogue
#pragma unroll
    for (int mt = 0; mt < 2; mt++)
#pragma unroll
        for (int nt = 0; nt < 4; nt++) {
            int row = bm + wm + mt * 16 + g;
            int col = bn + wn + nt * 8 + cq * 2;
            float2 v0 = make_float2(acc[mt][nt][0], acc[mt][nt][1]);
            float2 v1 = make_float2(acc[mt][nt][2], acc[mt][nt][3]);
            *(float2*)&C[(size_t)row * N + col]       = v0;
            *(float2*)&C[(size_t)(row + 8) * N + col] = v1;
        }
}

// ---------------------------------------------------------------------------
// RoPE in-place on q and k rows of g_qkv.
// ---------------------------------------------------------------------------
__global__ void rope_kernel(const int* __restrict__ positions)
{
    const int row = blockIdx.x;
    const int s  = row / (NH_ + NKV_);
    const int hh = row % (NH_ + NKV_);
    float* base = (hh < NH_)
        ? &g_qkv[(size_t)s * QKV_N_ + hh * HD_]
        : &g_qkv[(size_t)s * QKV_N_ + KOFF_ + (hh - NH_) * HD_];

    const int i = threadIdx.x;           // 0..31
    const float pos = (float)positions[s];
    const float inv_freq = powf(10000.0f, -(float)i / 32.0f);
    const float ang = pos * inv_freq;
    float c, sn;
    sincosf(ang, &sn, &c);
    const float x1 = base[i];
    const float x2 = base[i + 32];
    base[i]      = x1 * c - x2 * sn;
    base[i + 32] = x2 * c + x1 * sn;
}

// ---------------------------------------------------------------------------
// GQA causal attention with sinks. 8 queries/block, 256 threads, 2 keys/thread/iter.
// ---------------------------------------------------------------------------
__global__ __launch_bounds__(256)
void attn_kernel(const float* __restrict__ sinks)
{
    __shared__ float4 q4[QT_][16];       // 2 KB
    __shared__ float  sc[QT_][S_];       // 32 KB
    __shared__ float  red[QT_ * 256];    // 8 KB
    __shared__ float  m_s[QT_], den_s[QT_];

    const int h   = blockIdx.y;
    const int q0  = blockIdx.x * QT_;
    const int kv  = h >> 3;              // h / G, G = 8
    const int tid = threadIdx.x;
    const int wid = tid >> 5;
    const int lane = tid & 31;
    const float sink = sinks[h];
    const int nk = q0 + QT_;             // number of keys (causal upper bound)

    // load the 8 query rows
    for (int i = tid; i < QT_ * HD_; i += 256) {
        int iq = i >> 6, d = i & 63;
        ((float*)q4)[iq * 64 + d] = g_qkv[(size_t)(q0 + iq) * QKV_N_ + h * HD_ + d];
    }
    __syncthreads();

    // Phase 1: scores + local max (2 keys per thread per iteration)
    float lmax[QT_];
#pragma unroll
    for (int iq = 0; iq < QT_; iq++) lmax[iq] = -INFINITY;

    for (int k = 2 * tid; k < nk; k += 512) {
        const bool k1ok = (k + 1) < nk;
        const float4* K0 = (const float4*)&g_qkv[(size_t)k * QKV_N_ + KOFF_ + kv * HD_];
        const float4* K1 = (const float4*)&g_qkv[(size_t)(k1ok ? k + 1 : k) * QKV_N_ + KOFF_ + kv * HD_];
        float d0[QT_], d1[QT_];
#pragma unroll
        for (int iq = 0; iq < QT_; iq++) { d0[iq] = 0.f; d1[iq] = 0.f; }
#pragma unroll
        for (int c = 0; c < 16; c++) {
            float4 a = K0[c];
            float4 b = K1[c];
#pragma unroll
            for (int iq = 0; iq < QT_; iq++) {
                float4 qv = q4[iq][c];
                d0[iq] += qv.x * a.x + qv.y * a.y + qv.z * a.z + qv.w * a.w;
                d1[iq] += qv.x * b.x + qv.y * b.y + qv.z * b.z + qv.w * b.w;
            }
        }
#pragma unroll
        for (int iq = 0; iq < QT_; iq++) {
            float s0 = d0[iq] * SCALE_;
            if (k > q0 + iq) s0 = -INFINITY;
            sc[iq][k] = s0;
            lmax[iq] = fmaxf(lmax[iq], s0);
            if (k1ok) {
                float s1 = d1[iq] * SCALE_;
                if (k + 1 > q0 + iq) s1 = -INFINITY;
                sc[iq][k + 1] = s1;
                lmax[iq] = fmaxf(lmax[iq], s1);
            }
        }
    }
    // warp-shuffle max reduce, then cross-warp
#pragma unroll
    for (int iq = 0; iq < QT_; iq++) {
        float v = lmax[iq];
        v = fmaxf(v, __shfl_xor_sync(0xffffffffu, v, 16));
        v = fmaxf(v, __shfl_xor_sync(0xffffffffu, v, 8));
        v = fmaxf(v, __shfl_xor_sync(0xffffffffu, v, 4));
        v = fmaxf(v, __shfl_xor_sync(0xffffffffu, v, 2));
        v = fmaxf(v, __shfl_xor_sync(0xffffffffu, v, 1));
        if (lane == 0) red[iq * 8 + wid] = v;
    }
    __syncthreads();
    if (tid < QT_) {
        float m = sink;
        for (int w = 0; w < 8; w++) m = fmaxf(m, red[tid * 8 + w]);
        m_s[tid] = m;
    }
    __syncthreads();

    // Phase 2: exp + sum
    float lsum[QT_];
#pragma unroll
    for (int iq = 0; iq < QT_; iq++) lsum[iq] = 0.f;
    for (int k = tid; k < nk; k += 256) {
#pragma unroll
        for (int iq = 0; iq < QT_; iq++) {
            float s = sc[iq][k];
            float p = (s == -INFINITY) ? 0.f : __expf(s - m_s[iq]);
            sc[iq][k] = p;
            lsum[iq] += p;
        }
    }
#pragma unroll
    for (int iq = 0; iq < QT_; iq++) {
        float v = lsum[iq];
        v += __shfl_xor_sync(0xffffffffu, v, 16);
        v += __shfl_xor_sync(0xffffffffu, v, 8);
        v += __shfl_xor_sync(0xffffffffu, v, 4);
        v += __shfl_xor_sync(0xffffffffu, v, 2);
        v += __shfl_xor_sync(0xffffffffu, v, 1);
        if (lane == 0) red[iq * 8 + wid] = v;
    }
    __syncthreads();
    if (tid < QT_) {
        float sum = 0.f;
        for (int w = 0; w < 8; w++) sum += red[tid * 8 + w];
        den_s[tid] = sum + __expf(sink - m_s[tid]);
    }
    __syncthreads();

    // Phase 3: P @ V   (4 key-partitions x 64 dims)
    const int d    = tid & 63;
    const int part = tid >> 6;           // 0..3
    float acc[QT_];
#pragma unroll
    for (int iq = 0; iq < QT_; iq++) acc[iq] = 0.f;
    for (int k = part; k < nk; k += 4) {
        float v = g_qkv[(size_t)k * QKV_N_ + VOFF_ + kv * HD_ + d];
#pragma unroll
        for (int iq = 0; iq < QT_; iq++) acc[iq] += sc[iq][k] * v;
    }
    __syncthreads();
#pragma unroll
    for (int iq = 0; iq < QT_; iq++) red[iq * 256 + tid] = acc[iq];
    __syncthreads();
    if (tid < 64) {
#pragma unroll
        for (int iq = 0; iq < QT_; iq++) {
            float o = red[iq * 256 + d] + red[iq * 256 + d + 64]
                    + red[iq * 256 + d + 128] + red[iq * 256 + d + 192];
            g_attn[(size_t)(q0 + iq) * ATTN_N_ + h * HD_ + d] = o / den_s[iq];
        }
    }
}

// ---------------------------------------------------------------------------
// Launch
// ---------------------------------------------------------------------------
extern "C" void kernel_launch(void* const* d_in, const int* in_sizes, int n_in,
                              void* d_out, int out_size)
{
    const int*   positions = (const int*)d_in[0];
    const float* hidden    = (const float*)d_in[1];
    const float* qkv_w     = (const float*)d_in[2];
    const float* o_w       = (const float*)d_in[3];
    const float* sinks     = (const float*)d_in[4];
    float*       out       = (float*)d_out;

    void* p_qkv_v;  cudaGetSymbolAddress(&p_qkv_v,  g_qkv);
    void* p_attn_v; cudaGetSymbolAddress(&p_attn_v, g_attn);
    float* p_qkv  = (float*)p_qkv_v;
    float* p_attn = (float*)p_attn_v;

    // 1) QKV projection: [1024,2880] @ [5120,2880]^T -> [1024,5120]
    gemm_bf16x3_nt<<<dim3(QKV_N_ / BN, S_ / BM), 256>>>(hidden, qkv_w, p_qkv, S_, QKV_N_, H_);

    // 2) RoPE in place on q and k
    rope_kernel<<<S_ * (NH_ + NKV_), 32>>>(positions);

    // 3) Attention
    attn_kernel<<<dim3(S_ / QT_, NH_), 256>>>(sinks);

    // 4) O projection: [1024,4096] @ [2880,4096]^T -> [1024,2880]
    gemm_bf16x3_nt<<<dim3(H_ / BN, S_ / BM), 256>>>(p_attn, o_w, out, S_, H_, ATTN_N_);
}

// round 3
// speedup vs baseline: 2.2722x; 2.1340x over previous
#include <cuda_runtime.h>
#include <cuda_bf16.h>
#include <math.h>
#include <stdint.h>

// Problem constants
#define S_   1024
#define H_   2880
#define NH_  64
#define NKV_ 8
#define HD_  64
#define QKV_N_ 5120              // (NH + 2*NKV) * HD
#define KOFF_  4096              // NH*HD
#define VOFF_  4608              // NH*HD + NKV*HD
#define ATTN_N_ 4096             // NH*HD
#define SCALE_ 0.125f            // HD^-0.5

// Scratch (allocation-free: __device__ globals)
__device__ float g_qkv[S_ * QKV_N_];    // 20 MB
__device__ float g_attn[S_ * ATTN_N_];  // 16 MB

__device__ __forceinline__ void mma16816(float* c, const uint32_t* a, const uint32_t* b) {
    asm volatile(
        "mma.sync.aligned.m16n8k16.row.col.f32.bf16.bf16.f32 "
        "{%0,%1,%2,%3}, {%4,%5,%6,%7}, {%8,%9}, {%0,%1,%2,%3};\n"
        : "+f"(c[0]), "+f"(c[1]), "+f"(c[2]), "+f"(c[3])
        : "r"(a[0]), "r"(a[1]), "r"(a[2]), "r"(a[3]), "r"(b[0]), "r"(b[1]));
}

__device__ __forceinline__ void split2(float x, float y, uint32_t& hi, uint32_t& lo) {
    __nv_bfloat16 hx = __float2bfloat16(x);
    __nv_bfloat16 hy = __float2bfloat16(y);
    __nv_bfloat16 lx = __float2bfloat16(x - __bfloat162float(hx));
    __nv_bfloat16 ly = __float2bfloat16(y - __bfloat162float(hy));
    hi = ((uint32_t)__bfloat16_as_ushort(hy) << 16) | (uint32_t)__bfloat16_as_ushort(hx);
    lo = ((uint32_t)__bfloat16_as_ushort(ly) << 16) | (uint32_t)__bfloat16_as_ushort(lx);
}

// ---------------------------------------------------------------------------
// Tensor-core GEMM (NT), bf16 hi/lo 3-pass, fp32 accumulate, ping-pong smem.
// ---------------------------------------------------------------------------
#define BM 128
#define BN 64
#define BK 32
#define RSTRIDE 20

__global__ __launch_bounds__(256)
void gemm_bf16x3_nt(const float* __restrict__ A, const float* __restrict__ B,
                    float* __restrict__ C, int M, int N, int K)
{
    __shared__ uint32_t As[2][2][BM * RSTRIDE];   // [buf][hi/lo]
    __shared__ uint32_t Bs[2][2][BN * RSTRIDE];

    const int tid  = threadIdx.x;
    const int wid  = tid >> 5;
    const int lane = tid & 31;
    const int g    = lane >> 2;
    const int cq   = lane & 3;
    const int wm   = (wid & 3) * 32;
    const int wn   = (wid >> 2) * 32;
    const int bm   = blockIdx.y * BM;
    const int bn   = blockIdx.x * BN;

    const int a_row = tid >> 1;
    const int a_k   = (tid & 1) * 16;
    const int b_row = tid >> 2;
    const int b_k   = (tid & 3) * 8;

    float acc[2][4][4];
#pragma unroll
    for (int mt = 0; mt < 2; mt++)
#pragma unroll
        for (int nt = 0; nt < 4; nt++)
#pragma unroll
            for (int i = 0; i < 4; i++) acc[mt][nt][i] = 0.f;

    float4 ra[4], rb[2];
    const int ntile = K / BK;

    // prologue: load tile 0
#pragma unroll
    for (int j = 0; j < 4; j++)
        ra[j] = *(const float4*)&A[(size_t)(bm + a_row) * K + a_k + 4 * j];
#pragma unroll
    for (int j = 0; j < 2; j++)
        rb[j] = *(const float4*)&B[(size_t)(bn + b_row) * K + b_k + 4 * j];

    // store tile 0
    {
        uint32_t* ah = &As[0][0][a_row * RSTRIDE + (a_k >> 1)];
        uint32_t* al = &As[0][1][a_row * RSTRIDE + (a_k >> 1)];
#pragma unroll
        for (int j = 0; j < 4; j++) {
            uint32_t h0, l0, h1, l1;
            split2(ra[j].x, ra[j].y, h0, l0);
            split2(ra[j].z, ra[j].w, h1, l1);
            ah[2 * j] = h0; ah[2 * j + 1] = h1;
            al[2 * j] = l0; al[2 * j + 1] = l1;
        }
        uint32_t* bh = &Bs[0][0][b_row * RSTRIDE + (b_k >> 1)];
        uint32_t* bl = &Bs[0][1][b_row * RSTRIDE + (b_k >> 1)];
#pragma unroll
        for (int j = 0; j < 2; j++) {
            uint32_t h0, l0, h1, l1;
            split2(rb[j].x, rb[j].y, h0, l0);
            split2(rb[j].z, rb[j].w, h1, l1);
            bh[2 * j] = h0; bh[2 * j + 1] = h1;
            bl[2 * j] = l0; bl[2 * j + 1] = l1;
        }
    }
    __syncthreads();

    for (int t = 0; t < ntile; t++) {
        const int buf = t & 1;
        const bool more = (t + 1) < ntile;
        if (more) {
            const int k0 = (t + 1) * BK;
#pragma unroll
            for (int j = 0; j < 4; j++)
                ra[j] = *(const float4*)&A[(size_t)(bm + a_row) * K + k0 + a_k + 4 * j];
#pragma unroll
            for (int j = 0; j < 2; j++)
                rb[j] = *(const float4*)&B[(size_t)(bn + b_row) * K + k0 + b_k + 4 * j];
        }

#pragma unroll
        for (int kk = 0; kk < 2; kk++) {
            const int w0 = kk * 8 + cq;
            uint32_t ah[2][4], al[2][4], bh[4][2], bl[4][2];
#pragma unroll
            for (int mt = 0; mt < 2; mt++) {
                int r0 = (wm + mt * 16 + g) * RSTRIDE;
                int r8 = r0 + 8 * RSTRIDE;
                ah[mt][0] = As[buf][0][r0 + w0];
                ah[mt][1] = As[buf][0][r8 + w0];
                ah[mt][2] = As[buf][0][r0 + w0 + 4];
                ah[mt][3] = As[buf][0][r8 + w0 + 4];
                al[mt][0] = As[buf][1][r0 + w0];
                al[mt][1] = As[buf][1][r8 + w0];
                al[mt][2] = As[buf][1][r0 + w0 + 4];
                al[mt][3] = As[buf][1][r8 + w0 + 4];
            }
#pragma unroll
            for (int nt = 0; nt < 4; nt++) {
                int r0 = (wn + nt * 8 + g) * RSTRIDE;
                bh[nt][0] = Bs[buf][0][r0 + w0];
                bh[nt][1] = Bs[buf][0][r0 + w0 + 4];
                bl[nt][0] = Bs[buf][1][r0 + w0];
                bl[nt][1] = Bs[buf][1][r0 + w0 + 4];
            }
#pragma unroll
            for (int mt = 0; mt < 2; mt++)
#pragma unroll
                for (int nt = 0; nt < 4; nt++) {
                    mma16816(acc[mt][nt], ah[mt], bh[nt]);
                    mma16816(acc[mt][nt], ah[mt], bl[nt]);
                    mma16816(acc[mt][nt], al[mt], bh[nt]);
                }
        }

        if (more) {
            const int nb = buf ^ 1;
            uint32_t* ah = &As[nb][0][a_row * RSTRIDE + (a_k >> 1)];
            uint32_t* al = &As[nb][1][a_row * RSTRIDE + (a_k >> 1)];
#pragma unroll
            for (int j = 0; j < 4; j++) {
                uint32_t h0, l0, h1, l1;
                split2(ra[j].x, ra[j].y, h0, l0);
                split2(ra[j].z, ra[j].w, h1, l1);
                ah[2 * j] = h0; ah[2 * j + 1] = h1;
                al[2 * j] = l0; al[2 * j + 1] = l1;
            }
            uint32_t* bh = &Bs[nb][0][b_row * RSTRIDE + (b_k >> 1)];
            uint32_t* bl = &Bs[nb][1][b_row * RSTRIDE + (b_k >> 1)];
#pragma unroll
            for (int j = 0; j < 2; j++) {
                uint32_t h0, l0, h1, l1;
                split2(rb[j].x, rb[j].y, h0, l0);
                split2(rb[j].z, rb[j].w, h1, l1);
                bh[2 * j] = h0; bh[2 * j + 1] = h1;
                bl[2 * j] = l0; bl[2 * j + 1] = l1;
            }
        }
        __syncthreads();
    }

#pragma unroll
    for (int mt = 0; mt < 2; mt++)
#pragma unroll
        for (int nt = 0; nt < 4; nt++) {
            int row = bm + wm + mt * 16 + g;
            int col = bn + wn + nt * 8 + cq * 2;
            *(float2*)&C[(size_t)row * N + col]       = make_float2(acc[mt][nt][0], acc[mt][nt][1]);
            *(float2*)&C[(size_t)(row + 8) * N + col] = make_float2(acc[mt][nt][2], acc[mt][nt][3]);
        }
}

// ---------------------------------------------------------------------------
// RoPE in-place on q and k rows of g_qkv.
// ---------------------------------------------------------------------------
__global__ void rope_kernel(const int* __restrict__ positions)
{
    const int row = blockIdx.x;
    const int s  = row / (NH_ + NKV_);
    const int hh = row % (NH_ + NKV_);
    float* base = (hh < NH_)
        ? &g_qkv[(size_t)s * QKV_N_ + hh * HD_]
        : &g_qkv[(size_t)s * QKV_N_ + KOFF_ + (hh - NH_) * HD_];

    const int i = threadIdx.x;           // 0..31
    const float pos = (float)positions[s];
    const float inv_freq = powf(10000.0f, -(float)i / 32.0f);
    const float ang = pos * inv_freq;
    float c, sn;
    sincosf(ang, &sn, &c);
    const float x1 = base[i];
    const float x2 = base[i + 32];
    base[i]      = x1 * c - x2 * sn;
    base[i + 32] = x2 * c + x1 * sn;
}

// ---------------------------------------------------------------------------
// Flash attention with tensor cores (bf16 hi/lo 3-pass), online softmax, sinks.
// Block = (head, 64-query tile), 4 warps x 16 rows. KV tiles of 64 keys.
// ---------------------------------------------------------------------------
#define VSTR 36   // smem row stride in words: (4g+cq) mod 32 distinct -> conflict-free

__global__ __launch_bounds__(128)
void flash_attn(const float* __restrict__ sinks)
{
    __shared__ uint32_t Qs[2][64 * VSTR];  // [hi/lo][row][dim-pair word]
    __shared__ uint32_t Ks[2][64 * VSTR];  // [hi/lo][key][dim-pair word]
    __shared__ uint32_t Vs[2][64 * VSTR];  // [hi/lo][dim][key-pair word]

    const int h   = blockIdx.y;
    const int qt  = (S_ / 64 - 1) - blockIdx.x;   // heavy tiles first
    const int q0  = qt * 64;
    const int kv  = h >> 3;
    const int tid = threadIdx.x;
    const int wid = tid >> 5;
    const int lane = tid & 31;
    const int g   = lane >> 2;
    const int cq  = lane & 3;
    const float sink = sinks[h];

    // ---- stage Q tile ----
    {
        const int row = tid >> 1, e = tid & 1;
        const float* src = &g_qkv[(size_t)(q0 + row) * QKV_N_ + h * HD_ + e * 32];
        uint32_t* qh = &Qs[0][row * VSTR + e * 16];
        uint32_t* ql = &Qs[1][row * VSTR + e * 16];
#pragma unroll
        for (int c = 0; c < 8; c++) {
            float4 v = *(const float4*)&src[c * 4];
            uint32_t h0, l0, h1, l1;
            split2(v.x, v.y, h0, l0);
            split2(v.z, v.w, h1, l1);
            qh[2 * c] = h0; qh[2 * c + 1] = h1;
            ql[2 * c] = l0; ql[2 * c + 1] = l1;
        }
    }
    __syncthreads();

    // ---- Q fragments in registers (4 k-tiles, hi/lo) ----
    uint32_t qa[2][4][4];
    {
        const int r0 = (wid * 16 + g) * VSTR;
        const int r8 = r0 + 8 * VSTR;
#pragma unroll
        for (int s = 0; s < 2; s++)
#pragma unroll
            for (int kt = 0; kt < 4; kt++) {
                const int w0 = kt * 8 + cq;
                qa[s][kt][0] = Qs[s][r0 + w0];
                qa[s][kt][1] = Qs[s][r8 + w0];
                qa[s][kt][2] = Qs[s][r0 + w0 + 4];
                qa[s][kt][3] = Qs[s][r8 + w0 + 4];
            }
    }

    float oacc[8][4];
#pragma unroll
    for (int nt = 0; nt < 8; nt++)
#pragma unroll
        for (int i = 0; i < 4; i++) oacc[nt][i] = 0.f;
    float m0 = -INFINITY, m8 = -INFINITY;
    float l0 = 0.f, l8 = 0.f;

    const int row_g  = q0 + wid * 16 + g;
    const int row_g8 = row_g + 8;
    const int ntiles = qt + 1;

    for (int t = 0; t < ntiles; t++) {
        const int k0 = t * 64;
        __syncthreads();   // previous tile fully consumed before overwrite

        // stage K tile [key][dim]
        {
            const int key = tid >> 1, e = tid & 1;
            const float* src = &g_qkv[(size_t)(k0 + key) * QKV_N_ + KOFF_ + kv * HD_ + e * 32];
            uint32_t* kh = &Ks[0][key * VSTR + e * 16];
            uint32_t* kl = &Ks[1][key * VSTR + e * 16];
#pragma unroll
            for (int c = 0; c < 8; c++) {
                float4 v = *(const float4*)&src[c * 4];
                uint32_t h0, l0w, h1, l1;
                split2(v.x, v.y, h0, l0w);
                split2(v.z, v.w, h1, l1);
                kh[2 * c] = h0; kh[2 * c + 1] = h1;
                kl[2 * c] = l0w; kl[2 * c + 1] = l1;
            }
        }
        // stage V transposed: Vs[dim][key-pair word]
        {
            const int j = lane;          // key pair 0..31
#pragma unroll
            for (int i = 0; i < 4; i++) {
                const int d = wid * 16 + i * 4;
                const float* v0 = &g_qkv[(size_t)(k0 + 2 * j) * QKV_N_ + VOFF_ + kv * HD_ + d];
                const float* v1 = v0 + QKV_N_;
                float4 a = *(const float4*)v0;
                float4 b = *(const float4*)v1;
                uint32_t hw, lw;
                split2(a.x, b.x, hw, lw); Vs[0][(d + 0) * VSTR + j] = hw; Vs[1][(d + 0) * VSTR + j] = lw;
                split2(a.y, b.y, hw, lw); Vs[0][(d + 1) * VSTR + j] = hw; Vs[1][(d + 1) * VSTR + j] = lw;
                split2(a.z, b.z, hw, lw); Vs[0][(d + 2) * VSTR + j] = hw; Vs[1][(d + 2) * VSTR + j] = lw;
                split2(a.w, b.w, hw, lw); Vs[0][(d + 3) * VSTR + j] = hw; Vs[1][(d + 3) * VSTR + j] = lw;
            }
        }
        __syncthreads();

        // ---- S = Q K^T ----
        float sacc[8][4];
#pragma unroll
        for (int nt = 0; nt < 8; nt++)
#pragma unroll
            for (int i = 0; i < 4; i++) sacc[nt][i] = 0.f;

#pragma unroll
        for (int kt = 0; kt < 4; kt++) {
#pragma unroll
            for (int nt = 0; nt < 8; nt++) {
                const int r0 = (nt * 8 + g) * VSTR + kt * 8 + cq;
                uint32_t bhf[2], blf[2];
                bhf[0] = Ks[0][r0]; bhf[1] = Ks[0][r0 + 4];
                blf[0] = Ks[1][r0]; blf[1] = Ks[1][r0 + 4];
                mma16816(sacc[nt], qa[0][kt], bhf);
                mma16816(sacc[nt], qa[0][kt], blf);
                mma16816(sacc[nt], qa[1][kt], bhf);
            }
        }

        // ---- scale + causal mask (last tile only) ----
        const bool last = (t == ntiles - 1);
#pragma unroll
        for (int nt = 0; nt < 8; nt++) {
            const int c0 = k0 + nt * 8 + 2 * cq;
#pragma unroll
            for (int i = 0; i < 4; i++) sacc[nt][i] *= SCALE_;
            if (last) {
                if (c0     > row_g)  sacc[nt][0] = -INFINITY;
                if (c0 + 1 > row_g)  sacc[nt][1] = -INFINITY;
                if (c0     > row_g8) sacc[nt][2] = -INFINITY;
                if (c0 + 1 > row_g8) sacc[nt][3] = -INFINITY;
            }
        }

        // ---- online softmax update ----
        float tm0 = -INFINITY, tm8 = -INFINITY;
#pragma unroll
        for (int nt = 0; nt < 8; nt++) {
            tm0 = fmaxf(tm0, fmaxf(sacc[nt][0], sacc[nt][1]));
            tm8 = fmaxf(tm8, fmaxf(sacc[nt][2], sacc[nt][3]));
        }
        tm0 = fmaxf(tm0, __shfl_xor_sync(0xffffffffu, tm0, 1));
        tm0 = fmaxf(tm0, __shfl_xor_sync(0xffffffffu, tm0, 2));
        tm8 = fmaxf(tm8, __shfl_xor_sync(0xffffffffu, tm8, 1));
        tm8 = fmaxf(tm8, __shfl_xor_sync(0xffffffffu, tm8, 2));

        const float m0n = fmaxf(m0, tm0);
        const float m8n = fmaxf(m8, tm8);
        const float a0 = __expf(m0 - m0n);
        const float a8 = __expf(m8 - m8n);
        m0 = m0n; m8 = m8n;
        l0 *= a0; l8 *= a8;
#pragma unroll
        for (int nt = 0; nt < 8; nt++) {
            oacc[nt][0] *= a0; oacc[nt][1] *= a0;
            oacc[nt][2] *= a8; oacc[nt][3] *= a8;
        }

        // P = exp(S - m), accumulate partial l
#pragma unroll
        for (int nt = 0; nt < 8; nt++) {
            float p0 = (sacc[nt][0] == -INFINITY) ? 0.f : __expf(sacc[nt][0] - m0);
            float p1 = (sacc[nt][1] == -INFINITY) ? 0.f : __expf(sacc[nt][1] - m0);
            float p2 = (sacc[nt][2] == -INFINITY) ? 0.f : __expf(sacc[nt][2] - m8);
            float p3 = (sacc[nt][3] == -INFINITY) ? 0.f : __expf(sacc[nt][3] - m8);
            sacc[nt][0] = p0; sacc[nt][1] = p1; sacc[nt][2] = p2; sacc[nt][3] = p3;
            l0 += p0 + p1;
            l8 += p2 + p3;
        }

        // ---- O += P V ----
#pragma unroll
        for (int kt = 0; kt < 4; kt++) {
            uint32_t pah[4], pal[4];
            split2(sacc[2 * kt][0],     sacc[2 * kt][1],     pah[0], pal[0]);
            split2(sacc[2 * kt][2],     sacc[2 * kt][3],     pah[1], pal[1]);
            split2(sacc[2 * kt + 1][0], sacc[2 * kt + 1][1], pah[2], pal[2]);
            split2(sacc[2 * kt + 1][2], sacc[2 * kt + 1][3], pah[3], pal[3]);
#pragma unroll
            for (int nt = 0; nt < 8; nt++) {
                const int r0 = (nt * 8 + g) * VSTR + kt * 8 + cq;
                uint32_t vhf[2], vlf[2];
                vhf[0] = Vs[0][r0]; vhf[1] = Vs[0][r0 + 4];
                vlf[0] = Vs[1][r0]; vlf[1] = Vs[1][r0 + 4];
                mma16816(oacc[nt], pah, vhf);
                mma16816(oacc[nt], pah, vlf);
                mma16816(oacc[nt], pal, vhf);
            }
        }
    }

    // ---- finalize with sink ----
    {
        const float m0n = fmaxf(m0, sink);
        const float m8n = fmaxf(m8, sink);
        const float a0 = __expf(m0 - m0n);
        const float a8 = __expf(m8 - m8n);
        l0 *= a0; l8 *= a8;
        l0 += __shfl_xor_sync(0xffffffffu, l0, 1);
        l0 += __shfl_xor_sync(0xffffffffu, l0, 2);
        l8 += __shfl_xor_sync(0xffffffffu, l8, 1);
        l8 += __shfl_xor_sync(0xffffffffu, l8, 2);
        const float inv0 = a0 / (l0 + __expf(sink - m0n));
        const float inv8 = a8 / (l8 + __expf(sink - m8n));
#pragma unroll
        for (int nt = 0; nt < 8; nt++) {
            const int col = h * HD_ + nt * 8 + 2 * cq;
            *(float2*)&g_attn[(size_t)row_g  * ATTN_N_ + col] =
                make_float2(oacc[nt][0] * inv0, oacc[nt][1] * inv0);
            *(float2*)&g_attn[(size_t)row_g8 * ATTN_N_ + col] =
                make_float2(oacc[nt][2] * inv8, oacc[nt][3] * inv8);
        }
    }
}

// ---------------------------------------------------------------------------
// Launch
// ---------------------------------------------------------------------------
extern "C" void kernel_launch(void* const* d_in, const int* in_sizes, int n_in,
                              void* d_out, int out_size)
{
    const int*   positions = (const int*)d_in[0];
    const float* hidden    = (const float*)d_in[1];
    const float* qkv_w     = (const float*)d_in[2];
    const float* o_w       = (const float*)d_in[3];
    const float* sinks     = (const float*)d_in[4];
    float*       out       = (float*)d_out;

    void* p_qkv_v;  cudaGetSymbolAddress(&p_qkv_v,  g_qkv);
    void* p_attn_v; cudaGetSymbolAddress(&p_attn_v, g_attn);
    float* p_qkv  = (float*)p_qkv_v;
    float* p_attn = (float*)p_attn_v;

    // 1) QKV projection
    gemm_bf16x3_nt<<<dim3(QKV_N_ / BN, S_ / BM), 256>>>(hidden, qkv_w, p_qkv, S_, QKV_N_, H_);

    // 2) RoPE in place on q and k
    rope_kernel<<<S_ * (NH_ + NKV_), 32>>>(positions);

    // 3) Flash attention
    flash_attn<<<dim3(S_ / 64, NH_), 128>>>(sinks);

    // 4) O projection
    gemm_bf16x3_nt<<<dim3(H_ / BN, S_ / BM), 256>>>(p_attn, o_w, out, S_, H_, ATTN_N_);
}

// round 4
// speedup vs baseline: 3.0297x; 1.3333x over previous
#include <cuda_runtime.h>
#include <cuda_bf16.h>
#include <math.h>
#include <stdint.h>

// Problem constants
#define S_   1024
#define H_   2880
#define NH_  64
#define NKV_ 8
#define HD_  64
#define QKV_N_ 5120              // (NH + 2*NKV) * HD
#define KOFF_  4096              // NH*HD
#define VOFF_  4608              // NH*HD + NKV*HD
#define ATTN_N_ 4096             // NH*HD
#define SCALE_ 0.125f            // HD^-0.5

// ---------------------------------------------------------------------------
// Scratch (allocation-free: __device__ globals)
// ---------------------------------------------------------------------------
__device__ float g_qkv[S_ * QKV_N_];                    // 20 MB (pre-rope)
__device__ __nv_bfloat16 g_wqh[QKV_N_ * H_];            // qkv_w hi plane
__device__ __nv_bfloat16 g_wql[QKV_N_ * H_];            // qkv_w lo plane
__device__ __nv_bfloat16 g_woh[H_ * ATTN_N_];           // o_w hi
__device__ __nv_bfloat16 g_wol[H_ * ATTN_N_];           // o_w lo
__device__ __nv_bfloat16 g_xh[S_ * H_];                 // hidden hi
__device__ __nv_bfloat16 g_xl[S_ * H_];                 // hidden lo
__device__ __nv_bfloat16 g_qh[S_ * NH_ * HD_];          // roped Q hi
__device__ __nv_bfloat16 g_ql[S_ * NH_ * HD_];
__device__ __nv_bfloat16 g_kh[S_ * NKV_ * HD_];         // roped K hi
__device__ __nv_bfloat16 g_kl[S_ * NKV_ * HD_];
__device__ __nv_bfloat16 g_ah[S_ * ATTN_N_];            // attn out hi
__device__ __nv_bfloat16 g_al[S_ * ATTN_N_];

// ---------------------------------------------------------------------------
// Helpers
// ---------------------------------------------------------------------------
__device__ __forceinline__ void mma16816(float* c, const uint32_t* a, const uint32_t* b) {
    asm volatile(
        "mma.sync.aligned.m16n8k16.row.col.f32.bf16.bf16.f32 "
        "{%0,%1,%2,%3}, {%4,%5,%6,%7}, {%8,%9}, {%0,%1,%2,%3};\n"
        : "+f"(c[0]), "+f"(c[1]), "+f"(c[2]), "+f"(c[3])
        : "r"(a[0]), "r"(a[1]), "r"(a[2]), "r"(a[3]), "r"(b[0]), "r"(b[1]));
}

__device__ __forceinline__ void split2(float x, float y, uint32_t& hi, uint32_t& lo) {
    __nv_bfloat16 hx = __float2bfloat16(x);
    __nv_bfloat16 hy = __float2bfloat16(y);
    __nv_bfloat16 lx = __float2bfloat16(x - __bfloat162float(hx));
    __nv_bfloat16 ly = __float2bfloat16(y - __bfloat162float(hy));
    hi = ((uint32_t)__bfloat16_as_ushort(hy) << 16) | (uint32_t)__bfloat16_as_ushort(hx);
    lo = ((uint32_t)__bfloat16_as_ushort(ly) << 16) | (uint32_t)__bfloat16_as_ushort(lx);
}

__device__ __forceinline__ uint32_t smemu32(const void* p) {
    return (uint32_t)__cvta_generic_to_shared(p);
}

#define LDSM4(R0, R1, R2, R3, addr) \
    asm volatile("ldmatrix.sync.aligned.m8n8.x4.shared.b16 {%0,%1,%2,%3}, [%4];" \
                 : "=r"(R0), "=r"(R1), "=r"(R2), "=r"(R3) : "r"(addr))

#define CP16(dst, src) \
    asm volatile("cp.async.cg.shared.global [%0], [%1], 16;" :: "r"(dst), "l"(src))

// ---------------------------------------------------------------------------
// fp32 -> bf16 hi/lo plane split (vectorized)
// ---------------------------------------------------------------------------
__global__ __launch_bounds__(256)
void split_f32(const float* __restrict__ in, __nv_bfloat16* __restrict__ hi,
               __nv_bfloat16* __restrict__ lo, int n)
{
    int i = (blockIdx.x * 256 + threadIdx.x) * 4;
    if (i >= n) return;
    float4 v = *(const float4*)&in[i];
    uint32_t h0, l0, h1, l1;
    split2(v.x, v.y, h0, l0);
    split2(v.z, v.w, h1, l1);
    uint32_t* ph = (uint32_t*)&hi[i];
    uint32_t* pl = (uint32_t*)&lo[i];
    ph[0] = h0; ph[1] = h1;
    pl[0] = l0; pl[1] = l1;
}

// ---------------------------------------------------------------------------
// Tensor-core GEMM (NT) on pre-split bf16 planes. 3-pass hi/lo.
// C[m,n] = sum_k A[m,k]*B[n,k].  BM=128, BN=64, BK=32, 256 thr (8 warps).
// cp.async double-buffered smem, ldmatrix fragment loads.
// ---------------------------------------------------------------------------
#define BM 128
#define BN 64
#define BK 32
#define ASTR 40                       // elems/row (32 data + 8 pad) = 80B, 16B-aligned, conflict-free
#define BUF_ELEMS (2 * BM * ASTR + 2 * BN * ASTR)   // 15360 elems = 30720 B per buffer

__global__ __launch_bounds__(256)
void gemm_planes(const __nv_bfloat16* __restrict__ Ah, const __nv_bfloat16* __restrict__ Al,
                 const __nv_bfloat16* __restrict__ Bh, const __nv_bfloat16* __restrict__ Bl,
                 float* __restrict__ C, int M, int N, int K)
{
    extern __shared__ __nv_bfloat16 sm[];    // [2][BUF_ELEMS]

    const int tid  = threadIdx.x;
    const int wid  = tid >> 5;
    const int lane = tid & 31;
    const int g    = lane >> 2;
    const int cq   = lane & 3;
    const int wm   = (wid & 3) * 32;
    const int wn   = (wid >> 2) * 32;
    const int bm   = blockIdx.y * BM;
    const int bn   = blockIdx.x * BN;

    float acc[2][4][4];
#pragma unroll
    for (int mt = 0; mt < 2; mt++)
#pragma unroll
        for (int nt = 0; nt < 4; nt++)
#pragma unroll
            for (int i = 0; i < 4; i++) acc[mt][nt][i] = 0.f;

    const int ntile = K / BK;

    // --- async tile loader: 6 x 16B per thread ---
    auto load_tile = [&](int t, int buf) {
        const int k0 = t * BK;
        __nv_bfloat16* s = sm + buf * BUF_ELEMS;
#pragma unroll
        for (int i = 0; i < 4; i++) {                  // A: 1024 chunks
            int c   = tid + i * 256;
            int p   = c >> 9;
            int r   = (c & 511) >> 2;
            int col = (c & 3) * 8;
            const __nv_bfloat16* src = (p ? Al : Ah) + (size_t)(bm + r) * K + k0 + col;
            CP16(smemu32(s + p * BM * ASTR + r * ASTR + col), src);
        }
#pragma unroll
        for (int i = 0; i < 2; i++) {                  // B: 512 chunks
            int c   = tid + i * 256;
            int p   = c >> 8;
            int r   = (c & 255) >> 2;
            int col = (c & 3) * 8;
            const __nv_bfloat16* src = (p ? Bl : Bh) + (size_t)(bn + r) * K + k0 + col;
            CP16(smemu32(s + 2 * BM * ASTR + p * BN * ASTR + r * ASTR + col), src);
        }
        asm volatile("cp.async.commit_group;" ::);
    };

    load_tile(0, 0);

    const int lr  = lane & 15;
    const int hb  = (lane >> 4) * 8;
    const int l8  = lane & 7;
    const int sel = lane >> 3;

    for (int t = 0; t < ntile; t++) {
        asm volatile("cp.async.wait_group 0;" ::);
        __syncthreads();
        if (t + 1 < ntile) load_tile(t + 1, (t + 1) & 1);

        const __nv_bfloat16* s = sm + (t & 1) * BUF_ELEMS;
#pragma unroll
        for (int kk = 0; kk < 2; kk++) {
            uint32_t ah[2][4], alv[2][4];
#pragma unroll
            for (int mt = 0; mt < 2; mt++) {
                uint32_t addr = smemu32(s + (wm + mt * 16 + lr) * ASTR + kk * 16 + hb);
                LDSM4(ah[mt][0], ah[mt][1], ah[mt][2], ah[mt][3], addr);
                addr = smemu32(s + BM * ASTR + (wm + mt * 16 + lr) * ASTR + kk * 16 + hb);
                LDSM4(alv[mt][0], alv[mt][1], alv[mt][2], alv[mt][3], addr);
            }
#pragma unroll
            for (int np = 0; np < 2; np++) {
                const int brow = wn + np * 16 + ((sel >> 1) << 3) + l8;
                const int bcol = kk * 16 + (sel & 1) * 8;
                uint32_t bh[4], bl[4];
                LDSM4(bh[0], bh[1], bh[2], bh[3],
                      smemu32(s + 2 * BM * ASTR + brow * ASTR + bcol));
                LDSM4(bl[0], bl[1], bl[2], bl[3],
                      smemu32(s + 2 * BM * ASTR + BN * ASTR + brow * ASTR + bcol));
#pragma unroll
                for (int mt = 0; mt < 2; mt++) {
                    mma16816(acc[mt][2 * np],     ah[mt],  &bh[0]);
                    mma16816(acc[mt][2 * np],     ah[mt],  &bl[0]);
                    mma16816(acc[mt][2 * np],     alv[mt], &bh[0]);
                    mma16816(acc[mt][2 * np + 1], ah[mt],  &bh[2]);
                    mma16816(acc[mt][2 * np + 1], ah[mt],  &bl[2]);
                    mma16816(acc[mt][2 * np + 1], alv[mt], &bh[2]);
                }
            }
        }
    }

#pragma unroll
    for (int mt = 0; mt < 2; mt++)
#pragma unroll
        for (int nt = 0; nt < 4; nt++) {
            int row = bm + wm + mt * 16 + g;
            int col = bn + wn + nt * 8 + cq * 2;
            *(float2*)&C[(size_t)row * N + col]       = make_float2(acc[mt][nt][0], acc[mt][nt][1]);
            *(float2*)&C[(size_t)(row + 8) * N + col] = make_float2(acc[mt][nt][2], acc[mt][nt][3]);
        }
}

// ---------------------------------------------------------------------------
// RoPE + split to bf16 planes. One 32-thread block per (s, q-or-k head).
// Reads g_qkv fp32 (pre-rope), writes g_qh/ql or g_kh/kl.
// ---------------------------------------------------------------------------
__global__ void rope_split(const int* __restrict__ positions)
{
    const int row = blockIdx.x;                  // 0 .. S*(NH+NKV)-1
    const int s  = row / (NH_ + NKV_);
    const int hh = row % (NH_ + NKV_);
    const int i  = threadIdx.x;                  // 0..31

    const float pos = (float)positions[s];
    const float inv_freq = powf(10000.0f, -(float)i / 32.0f);
    const float ang = pos * inv_freq;
    float c, sn;
    sincosf(ang, &sn, &c);

    const float* src;
    __nv_bfloat16 *dh, *dl;
    if (hh < NH_) {
        src = &g_qkv[(size_t)s * QKV_N_ + hh * HD_];
        dh = &g_qh[(size_t)s * (NH_ * HD_) + hh * HD_];
        dl = &g_ql[(size_t)s * (NH_ * HD_) + hh * HD_];
    } else {
        const int kvh = hh - NH_;
        src = &g_qkv[(size_t)s * QKV_N_ + KOFF_ + kvh * HD_];
        dh = &g_kh[(size_t)s * (NKV_ * HD_) + kvh * HD_];
        dl = &g_kl[(size_t)s * (NKV_ * HD_) + kvh * HD_];
    }
    const float x1 = src[i];
    const float x2 = src[i + 32];
    const float r1 = x1 * c - x2 * sn;
    const float r2 = x2 * c + x1 * sn;
    __nv_bfloat16 h1 = __float2bfloat16(r1);
    __nv_bfloat16 h2 = __float2bfloat16(r2);
    dh[i]      = h1;
    dh[i + 32] = h2;
    dl[i]      = __float2bfloat16(r1 - __bfloat162float(h1));
    dl[i + 32] = __float2bfloat16(r2 - __bfloat162float(h2));
}

// ---------------------------------------------------------------------------
// Flash attention (tensor cores, hi/lo 3-pass), online softmax, sinks.
// Q/K staged from pre-split planes; V split from g_qkv (transposed staging).
// Output written as bf16 hi/lo planes for the O-projection.
// ---------------------------------------------------------------------------
#define VSTR 36

__global__ __launch_bounds__(128)
void flash_attn(const float* __restrict__ sinks)
{
    __shared__ uint32_t Qs[2][64 * VSTR];
    __shared__ uint32_t Ks[2][64 * VSTR];
    __shared__ uint32_t Vs[2][64 * VSTR];

    const int h   = blockIdx.y;
    const int qt  = (S_ / 64 - 1) - blockIdx.x;   // heavy tiles first
    const int q0  = qt * 64;
    const int kv  = h >> 3;
    const int tid = threadIdx.x;
    const int wid = tid >> 5;
    const int lane = tid & 31;
    const int g   = lane >> 2;
    const int cq  = lane & 3;
    const float sink = sinks[h];

    // ---- stage Q tile from planes (plain word copies) ----
    {
        const int row = tid >> 1, e = tid & 1;
        const uint32_t* qh = (const uint32_t*)&g_qh[(size_t)(q0 + row) * (NH_ * HD_) + h * HD_ + e * 32];
        const uint32_t* ql = (const uint32_t*)&g_ql[(size_t)(q0 + row) * (NH_ * HD_) + h * HD_ + e * 32];
#pragma unroll
        for (int w = 0; w < 16; w++) {
            Qs[0][row * VSTR + e * 16 + w] = qh[w];
            Qs[1][row * VSTR + e * 16 + w] = ql[w];
        }
    }
    __syncthreads();

    // ---- Q fragments in registers ----
    uint32_t qa[2][4][4];
    {
        const int r0 = (wid * 16 + g) * VSTR;
        const int r8 = r0 + 8 * VSTR;
#pragma unroll
        for (int p = 0; p < 2; p++)
#pragma unroll
            for (int kt = 0; kt < 4; kt++) {
                const int w0 = kt * 8 + cq;
                qa[p][kt][0] = Qs[p][r0 + w0];
                qa[p][kt][1] = Qs[p][r8 + w0];
                qa[p][kt][2] = Qs[p][r0 + w0 + 4];
                qa[p][kt][3] = Qs[p][r8 + w0 + 4];
            }
    }

    float oacc[8][4];
#pragma unroll
    for (int nt = 0; nt < 8; nt++)
#pragma unroll
        for (int i = 0; i < 4; i++) oacc[nt][i] = 0.f;
    float m0 = -INFINITY, m8 = -INFINITY;
    float l0 = 0.f, l8 = 0.f;

    const int row_g  = q0 + wid * 16 + g;
    const int row_g8 = row_g + 8;
    const int ntiles = qt + 1;

    for (int t = 0; t < ntiles; t++) {
        const int k0 = t * 64;
        __syncthreads();

        // stage K tile from planes
        {
            const int key = tid >> 1, e = tid & 1;
            const uint32_t* kh = (const uint32_t*)&g_kh[(size_t)(k0 + key) * (NKV_ * HD_) + kv * HD_ + e * 32];
            const uint32_t* kl = (const uint32_t*)&g_kl[(size_t)(k0 + key) * (NKV_ * HD_) + kv * HD_ + e * 32];
#pragma unroll
            for (int w = 0; w < 16; w++) {
                Ks[0][key * VSTR + e * 16 + w] = kh[w];
                Ks[1][key * VSTR + e * 16 + w] = kl[w];
            }
        }
        // stage V transposed: Vs[dim][key-pair word] (split from fp32 g_qkv)
        {
            const int j = lane;
#pragma unroll
            for (int i = 0; i < 4; i++) {
                const int d = wid * 16 + i * 4;
                const float* v0 = &g_qkv[(size_t)(k0 + 2 * j) * QKV_N_ + VOFF_ + kv * HD_ + d];
                const float* v1 = v0 + QKV_N_;
                float4 a = *(const float4*)v0;
                float4 b = *(const float4*)v1;
                uint32_t hw, lw;
                split2(a.x, b.x, hw, lw); Vs[0][(d + 0) * VSTR + j] = hw; Vs[1][(d + 0) * VSTR + j] = lw;
                split2(a.y, b.y, hw, lw); Vs[0][(d + 1) * VSTR + j] = hw; Vs[1][(d + 1) * VSTR + j] = lw;
                split2(a.z, b.z, hw, lw); Vs[0][(d + 2) * VSTR + j] = hw; Vs[1][(d + 2) * VSTR + j] = lw;
                split2(a.w, b.w, hw, lw); Vs[0][(d + 3) * VSTR + j] = hw; Vs[1][(d + 3) * VSTR + j] = lw;
            }
        }
        __syncthreads();

        // ---- S = Q K^T ----
        float sacc[8][4];
#pragma unroll
        for (int nt = 0; nt < 8; nt++)
#pragma unroll
            for (int i = 0; i < 4; i++) sacc[nt][i] = 0.f;

#pragma unroll
        for (int kt = 0; kt < 4; kt++) {
#pragma unroll
            for (int nt = 0; nt < 8; nt++) {
                const int r0 = (nt * 8 + g) * VSTR + kt * 8 + cq;
                uint32_t bhf[2], blf[2];
                bhf[0] = Ks[0][r0]; bhf[1] = Ks[0][r0 + 4];
                blf[0] = Ks[1][r0]; blf[1] = Ks[1][r0 + 4];
                mma16816(sacc[nt], qa[0][kt], bhf);
                mma16816(sacc[nt], qa[0][kt], blf);
                mma16816(sacc[nt], qa[1][kt], bhf);
            }
        }

        // ---- scale + causal mask (last tile only) ----
        const bool last = (t == ntiles - 1);
#pragma unroll
        for (int nt = 0; nt < 8; nt++) {
            const int c0 = k0 + nt * 8 + 2 * cq;
#pragma unroll
            for (int i = 0; i < 4; i++) sacc[nt][i] *= SCALE_;
            if (last) {
                if (c0     > row_g)  sacc[nt][0] = -INFINITY;
                if (c0 + 1 > row_g)  sacc[nt][1] = -INFINITY;
                if (c0     > row_g8) sacc[nt][2] = -INFINITY;
                if (c0 + 1 > row_g8) sacc[nt][3] = -INFINITY;
            }
        }

        // ---- online softmax update ----
        float tm0 = -INFINITY, tm8 = -INFINITY;
#pragma unroll
        for (int nt = 0; nt < 8; nt++) {
            tm0 = fmaxf(tm0, fmaxf(sacc[nt][0], sacc[nt][1]));
            tm8 = fmaxf(tm8, fmaxf(sacc[nt][2], sacc[nt][3]));
        }
        tm0 = fmaxf(tm0, __shfl_xor_sync(0xffffffffu, tm0, 1));
        tm0 = fmaxf(tm0, __shfl_xor_sync(0xffffffffu, tm0, 2));
        tm8 = fmaxf(tm8, __shfl_xor_sync(0xffffffffu, tm8, 1));
        tm8 = fmaxf(tm8, __shfl_xor_sync(0xffffffffu, tm8, 2));

        const float m0n = fmaxf(m0, tm0);
        const float m8n = fmaxf(m8, tm8);
        const float a0 = __expf(m0 - m0n);
        const float a8 = __expf(m8 - m8n);
        m0 = m0n; m8 = m8n;
        l0 *= a0; l8 *= a8;
#pragma unroll
        for (int nt = 0; nt < 8; nt++) {
            oacc[nt][0] *= a0; oacc[nt][1] *= a0;
            oacc[nt][2] *= a8; oacc[nt][3] *= a8;
        }

#pragma unroll
        for (int nt = 0; nt < 8; nt++) {
            float p0 = (sacc[nt][0] == -INFINITY) ? 0.f : __expf(sacc[nt][0] - m0);
            float p1 = (sacc[nt][1] == -INFINITY) ? 0.f : __expf(sacc[nt][1] - m0);
            float p2 = (sacc[nt][2] == -INFINITY) ? 0.f : __expf(sacc[nt][2] - m8);
            float p3 = (sacc[nt][3] == -INFINITY) ? 0.f : __expf(sacc[nt][3] - m8);
            sacc[nt][0] = p0; sacc[nt][1] = p1; sacc[nt][2] = p2; sacc[nt][3] = p3;
            l0 += p0 + p1;
            l8 += p2 + p3;
        }

        // ---- O += P V ----
#pragma unroll
        for (int kt = 0; kt < 4; kt++) {
            uint32_t pah[4], pal[4];
            split2(sacc[2 * kt][0],     sacc[2 * kt][1],     pah[0], pal[0]);
            split2(sacc[2 * kt][2],     sacc[2 * kt][3],     pah[1], pal[1]);
            split2(sacc[2 * kt + 1][0], sacc[2 * kt + 1][1], pah[2], pal[2]);
            split2(sacc[2 * kt + 1][2], sacc[2 * kt + 1][3], pah[3], pal[3]);
#pragma unroll
            for (int nt = 0; nt < 8; nt++) {
                const int r0 = (nt * 8 + g) * VSTR + kt * 8 + cq;
                uint32_t vhf[2], vlf[2];
                vhf[0] = Vs[0][r0]; vhf[1] = Vs[0][r0 + 4];
                vlf[0] = Vs[1][r0]; vlf[1] = Vs[1][r0 + 4];
                mma16816(oacc[nt], pah, vhf);
                mma16816(oacc[nt], pah, vlf);
                mma16816(oacc[nt], pal, vhf);
            }
        }
    }

    // ---- finalize with sink; write bf16 hi/lo planes ----
    {
        const float m0n = fmaxf(m0, sink);
        const float m8n = fmaxf(m8, sink);
        const float a0 = __expf(m0 - m0n);
        const float a8 = __expf(m8 - m8n);
        l0 *= a0; l8 *= a8;
        l0 += __shfl_xor_sync(0xffffffffu, l0, 1);
        l0 += __shfl_xor_sync(0xffffffffu, l0, 2);
        l8 += __shfl_xor_sync(0xffffffffu, l8, 1);
        l8 += __shfl_xor_sync(0xffffffffu, l8, 2);
        const float inv0 = a0 / (l0 + __expf(sink - m0n));
        const float inv8 = a8 / (l8 + __expf(sink - m8n));
#pragma unroll
        for (int nt = 0; nt < 8; nt++) {
            const int col = h * HD_ + nt * 8 + 2 * cq;
            uint32_t hw, lw;
            split2(oacc[nt][0] * inv0, oacc[nt][1] * inv0, hw, lw);
            *(uint32_t*)&g_ah[(size_t)row_g * ATTN_N_ + col] = hw;
            *(uint32_t*)&g_al[(size_t)row_g * ATTN_N_ + col] = lw;
            split2(oacc[nt][2] * inv8, oacc[nt][3] * inv8, hw, lw);
            *(uint32_t*)&g_ah[(size_t)row_g8 * ATTN_N_ + col] = hw;
            *(uint32_t*)&g_al[(size_t)row_g8 * ATTN_N_ + col] = lw;
        }
    }
}

// ---------------------------------------------------------------------------
// Launch
// ---------------------------------------------------------------------------
extern "C" void kernel_launch(void* const* d_in, const int* in_sizes, int n_in,
                              void* d_out, int out_size)
{
    const int*   positions = (const int*)d_in[0];
    const float* hidden    = (const float*)d_in[1];
    const float* qkv_w     = (const float*)d_in[2];
    const float* o_w       = (const float*)d_in[3];
    const float* sinks     = (const float*)d_in[4];
    float*       out       = (float*)d_out;

    static bool attr_done = false;
    if (!attr_done) {
        cudaFuncSetAttribute(gemm_planes, cudaFuncAttributeMaxDynamicSharedMemorySize,
                             2 * BUF_ELEMS * (int)sizeof(__nv_bfloat16));
        attr_done = true;
    }

    void *p;
    cudaGetSymbolAddress(&p, g_qkv);  float* qkv = (float*)p;
    cudaGetSymbolAddress(&p, g_wqh);  __nv_bfloat16* wqh = (__nv_bfloat16*)p;
    cudaGetSymbolAddress(&p, g_wql);  __nv_bfloat16* wql = (__nv_bfloat16*)p;
    cudaGetSymbolAddress(&p, g_woh);  __nv_bfloat16* woh = (__nv_bfloat16*)p;
    cudaGetSymbolAddress(&p, g_wol);  __nv_bfloat16* wol = (__nv_bfloat16*)p;
    cudaGetSymbolAddress(&p, g_xh);   __nv_bfloat16* xh  = (__nv_bfloat16*)p;
    cudaGetSymbolAddress(&p, g_xl);   __nv_bfloat16* xl  = (__nv_bfloat16*)p;
    cudaGetSymbolAddress(&p, g_ah);   __nv_bfloat16* ah  = (__nv_bfloat16*)p;
    cudaGetSymbolAddress(&p, g_al);   __nv_bfloat16* al  = (__nv_bfloat16*)p;

    const int smem = 2 * BUF_ELEMS * (int)sizeof(__nv_bfloat16);

    // 0) pre-split weights + activations to bf16 planes
    split_f32<<<(QKV_N_ * H_) / 1024, 256>>>(qkv_w, wqh, wql, QKV_N_ * H_);
    split_f32<<<(H_ * ATTN_N_) / 1024, 256>>>(o_w, woh, wol, H_ * ATTN_N_);
    split_f32<<<(S_ * H_) / 1024, 256>>>(hidden, xh, xl, S_ * H_);

    // 1) QKV projection: [1024,2880] @ [5120,2880]^T -> g_qkv fp32
    gemm_planes<<<dim3(QKV_N_ / BN, S_ / BM), 256, smem>>>(xh, xl, wqh, wql, qkv, S_, QKV_N_, H_);

    // 2) RoPE + split Q/K to planes
    rope_split<<<S_ * (NH_ + NKV_), 32>>>(positions);

    // 3) Flash attention -> attn planes
    flash_attn<<<dim3(S_ / 64, NH_), 128>>>(sinks);

    // 4) O projection: attn planes @ o_w planes -> out fp32
    gemm_planes<<<dim3(H_ / BN, S_ / BM), 256, smem>>>(ah, al, woh, wol, out, S_, H_, ATTN_N_);
}

// round 5
// speedup vs baseline: 3.0408x; 1.0037x over previous
#include <cuda_runtime.h>
#include <cuda_bf16.h>
#include <math.h>
#include <stdint.h>

// Problem constants
#define S_   1024
#define H_   2880
#define NH_  64
#define NKV_ 8
#define HD_  64
#define QKV_N_ 5120              // (NH + 2*NKV) * HD
#define KOFF_  4096              // NH*HD
#define VOFF_  4608              // NH*HD + NKV*HD
#define ATTN_N_ 4096             // NH*HD
#define SCALE_ 0.125f            // HD^-0.5

// ---------------------------------------------------------------------------
// Scratch (allocation-free: __device__ globals)
// ---------------------------------------------------------------------------
__device__ float g_qkv[S_ * QKV_N_];                    // 20 MB (pre-rope)
__device__ __nv_bfloat16 g_wqh[QKV_N_ * H_];            // qkv_w hi plane
__device__ __nv_bfloat16 g_wql[QKV_N_ * H_];            // qkv_w lo plane
__device__ __nv_bfloat16 g_woh[H_ * ATTN_N_];           // o_w hi
__device__ __nv_bfloat16 g_wol[H_ * ATTN_N_];           // o_w lo
__device__ __nv_bfloat16 g_xh[S_ * H_];                 // hidden hi
__device__ __nv_bfloat16 g_xl[S_ * H_];                 // hidden lo
__device__ __nv_bfloat16 g_qh[S_ * NH_ * HD_];          // roped Q hi
__device__ __nv_bfloat16 g_ql[S_ * NH_ * HD_];
__device__ __nv_bfloat16 g_kh[S_ * NKV_ * HD_];         // roped K hi
__device__ __nv_bfloat16 g_kl[S_ * NKV_ * HD_];
__device__ __nv_bfloat16 g_ah[S_ * ATTN_N_];            // attn out hi
__device__ __nv_bfloat16 g_al[S_ * ATTN_N_];

// ---------------------------------------------------------------------------
// Helpers
// ---------------------------------------------------------------------------
__device__ __forceinline__ void mma16816(float* c, const uint32_t* a, const uint32_t* b) {
    asm volatile(
        "mma.sync.aligned.m16n8k16.row.col.f32.bf16.bf16.f32 "
        "{%0,%1,%2,%3}, {%4,%5,%6,%7}, {%8,%9}, {%0,%1,%2,%3};\n"
        : "+f"(c[0]), "+f"(c[1]), "+f"(c[2]), "+f"(c[3])
        : "r"(a[0]), "r"(a[1]), "r"(a[2]), "r"(a[3]), "r"(b[0]), "r"(b[1]));
}

__device__ __forceinline__ void split2(float x, float y, uint32_t& hi, uint32_t& lo) {
    __nv_bfloat16 hx = __float2bfloat16(x);
    __nv_bfloat16 hy = __float2bfloat16(y);
    __nv_bfloat16 lx = __float2bfloat16(x - __bfloat162float(hx));
    __nv_bfloat16 ly = __float2bfloat16(y - __bfloat162float(hy));
    hi = ((uint32_t)__bfloat16_as_ushort(hy) << 16) | (uint32_t)__bfloat16_as_ushort(hx);
    lo = ((uint32_t)__bfloat16_as_ushort(ly) << 16) | (uint32_t)__bfloat16_as_ushort(lx);
}

__device__ __forceinline__ uint32_t smemu32(const void* p) {
    return (uint32_t)__cvta_generic_to_shared(p);
}

#define LDSM4(R0, R1, R2, R3, addr) \
    asm volatile("ldmatrix.sync.aligned.m8n8.x4.shared.b16 {%0,%1,%2,%3}, [%4];" \
                 : "=r"(R0), "=r"(R1), "=r"(R2), "=r"(R3) : "r"(addr))

#define CP16(dst, src) \
    asm volatile("cp.async.cg.shared.global [%0], [%1], 16;" :: "r"(dst), "l"(src))

// ---------------------------------------------------------------------------
// fp32 -> bf16 hi/lo plane split (vectorized)
// ---------------------------------------------------------------------------
__global__ __launch_bounds__(256)
void split_f32(const float* __restrict__ in, __nv_bfloat16* __restrict__ hi,
               __nv_bfloat16* __restrict__ lo, int n)
{
    int i = (blockIdx.x * 256 + threadIdx.x) * 4;
    if (i >= n) return;
    float4 v = *(const float4*)&in[i];
    uint32_t h0, l0, h1, l1;
    split2(v.x, v.y, h0, l0);
    split2(v.z, v.w, h1, l1);
    uint32_t* ph = (uint32_t*)&hi[i];
    uint32_t* pl = (uint32_t*)&lo[i];
    ph[0] = h0; ph[1] = h1;
    pl[0] = l0; pl[1] = l1;
}

// ---------------------------------------------------------------------------
// Tensor-core GEMM (NT) on pre-split bf16 planes. 3-pass hi/lo.
// C[m,n] = sum_k A[m,k]*B[n,k].  BM=128, BN=64, BK=32, 256 thr (8 warps).
// cp.async double-buffered smem, ldmatrix fragment loads.
// ---------------------------------------------------------------------------
#define BM 128
#define BN 64
#define BK 32
#define ASTR 40                       // elems/row (32 data + 8 pad) = 80B, 16B-aligned, conflict-free
#define BUF_ELEMS (2 * BM * ASTR + 2 * BN * ASTR)   // 15360 elems = 30720 B per buffer

__global__ __launch_bounds__(256)
void gemm_planes(const __nv_bfloat16* __restrict__ Ah, const __nv_bfloat16* __restrict__ Al,
                 const __nv_bfloat16* __restrict__ Bh, const __nv_bfloat16* __restrict__ Bl,
                 float* __restrict__ C, int M, int N, int K)
{
    extern __shared__ __nv_bfloat16 sm[];    // [2][BUF_ELEMS]

    const int tid  = threadIdx.x;
    const int wid  = tid >> 5;
    const int lane = tid & 31;
    const int g    = lane >> 2;
    const int cq   = lane & 3;
    const int wm   = (wid & 3) * 32;
    const int wn   = (wid >> 2) * 32;
    const int bm   = blockIdx.y * BM;
    const int bn   = blockIdx.x * BN;

    float acc[2][4][4];
#pragma unroll
    for (int mt = 0; mt < 2; mt++)
#pragma unroll
        for (int nt = 0; nt < 4; nt++)
#pragma unroll
            for (int i = 0; i < 4; i++) acc[mt][nt][i] = 0.f;

    const int ntile = K / BK;

    // --- async tile loader: 6 x 16B per thread ---
    auto load_tile = [&](int t, int buf) {
        const int k0 = t * BK;
        __nv_bfloat16* s = sm + buf * BUF_ELEMS;
#pragma unroll
        for (int i = 0; i < 4; i++) {                  // A: 1024 chunks
            int c   = tid + i * 256;
            int p   = c >> 9;
            int r   = (c & 511) >> 2;
            int col = (c & 3) * 8;
            const __nv_bfloat16* src = (p ? Al : Ah) + (size_t)(bm + r) * K + k0 + col;
            CP16(smemu32(s + p * BM * ASTR + r * ASTR + col), src);
        }
#pragma unroll
        for (int i = 0; i < 2; i++) {                  // B: 512 chunks
            int c   = tid + i * 256;
            int p   = c >> 8;
            int r   = (c & 255) >> 2;
            int col = (c & 3) * 8;
            const __nv_bfloat16* src = (p ? Bl : Bh) + (size_t)(bn + r) * K + k0 + col;
            CP16(smemu32(s + 2 * BM * ASTR + p * BN * ASTR + r * ASTR + col), src);
        }
        asm volatile("cp.async.commit_group;" ::);
    };

    load_tile(0, 0);

    const int lr  = lane & 15;
    const int hb  = (lane >> 4) * 8;
    const int l8  = lane & 7;
    const int sel = lane >> 3;

    for (int t = 0; t < ntile; t++) {
        asm volatile("cp.async.wait_group 0;" ::);
        __syncthreads();
        if (t + 1 < ntile) load_tile(t + 1, (t + 1) & 1);

        const __nv_bfloat16* s = sm + (t & 1) * BUF_ELEMS;
#pragma unroll
        for (int kk = 0; kk < 2; kk++) {
            uint32_t ah[2][4], alv[2][4];
#pragma unroll
            for (int mt = 0; mt < 2; mt++) {
                uint32_t addr = smemu32(s + (wm + mt * 16 + lr) * ASTR + kk * 16 + hb);
                LDSM4(ah[mt][0], ah[mt][1], ah[mt][2], ah[mt][3], addr);
                addr = smemu32(s + BM * ASTR + (wm + mt * 16 + lr) * ASTR + kk * 16 + hb);
                LDSM4(alv[mt][0], alv[mt][1], alv[mt][2], alv[mt][3], addr);
            }
#pragma unroll
            for (int np = 0; np < 2; np++) {
                const int brow = wn + np * 16 + ((sel >> 1) << 3) + l8;
                const int bcol = kk * 16 + (sel & 1) * 8;
                uint32_t bh[4], bl[4];
                LDSM4(bh[0], bh[1], bh[2], bh[3],
                      smemu32(s + 2 * BM * ASTR + brow * ASTR + bcol));
                LDSM4(bl[0], bl[1], bl[2], bl[3],
                      smemu32(s + 2 * BM * ASTR + BN * ASTR + brow * ASTR + bcol));
#pragma unroll
                for (int mt = 0; mt < 2; mt++) {
                    mma16816(acc[mt][2 * np],     ah[mt],  &bh[0]);
                    mma16816(acc[mt][2 * np],     ah[mt],  &bl[0]);
                    mma16816(acc[mt][2 * np],     alv[mt], &bh[0]);
                    mma16816(acc[mt][2 * np + 1], ah[mt],  &bh[2]);
                    mma16816(acc[mt][2 * np + 1], ah[mt],  &bl[2]);
                    mma16816(acc[mt][2 * np + 1], alv[mt], &bh[2]);
                }
            }
        }
    }

#pragma unroll
    for (int mt = 0; mt < 2; mt++)
#pragma unroll
        for (int nt = 0; nt < 4; nt++) {
            int row = bm + wm + mt * 16 + g;
            int col = bn + wn + nt * 8 + cq * 2;
            *(float2*)&C[(size_t)row * N + col]       = make_float2(acc[mt][nt][0], acc[mt][nt][1]);
            *(float2*)&C[(size_t)(row + 8) * N + col] = make_float2(acc[mt][nt][2], acc[mt][nt][3]);
        }
}

// ---------------------------------------------------------------------------
// RoPE + split to bf16 planes. One 32-thread block per (s, q-or-k head).
// Reads g_qkv fp32 (pre-rope), writes g_qh/ql or g_kh/kl.
// ---------------------------------------------------------------------------
__global__ void rope_split(const int* __restrict__ positions)
{
    const int row = blockIdx.x;                  // 0 .. S*(NH+NKV)-1
    const int s  = row / (NH_ + NKV_);
    const int hh = row % (NH_ + NKV_);
    const int i  = threadIdx.x;                  // 0..31

    const float pos = (float)positions[s];
    const float inv_freq = powf(10000.0f, -(float)i / 32.0f);
    const float ang = pos * inv_freq;
    float c, sn;
    sincosf(ang, &sn, &c);

    const float* src;
    __nv_bfloat16 *dh, *dl;
    if (hh < NH_) {
        src = &g_qkv[(size_t)s * QKV_N_ + hh * HD_];
        dh = &g_qh[(size_t)s * (NH_ * HD_) + hh * HD_];
        dl = &g_ql[(size_t)s * (NH_ * HD_) + hh * HD_];
    } else {
        const int kvh = hh - NH_;
        src = &g_qkv[(size_t)s * QKV_N_ + KOFF_ + kvh * HD_];
        dh = &g_kh[(size_t)s * (NKV_ * HD_) + kvh * HD_];
        dl = &g_kl[(size_t)s * (NKV_ * HD_) + kvh * HD_];
    }
    const float x1 = src[i];
    const float x2 = src[i + 32];
    const float r1 = x1 * c - x2 * sn;
    const float r2 = x2 * c + x1 * sn;
    __nv_bfloat16 h1 = __float2bfloat16(r1);
    __nv_bfloat16 h2 = __float2bfloat16(r2);
    dh[i]      = h1;
    dh[i + 32] = h2;
    dl[i]      = __float2bfloat16(r1 - __bfloat162float(h1));
    dl[i + 32] = __float2bfloat16(r2 - __bfloat162float(h2));
}

// ---------------------------------------------------------------------------
// Flash attention (tensor cores, hi/lo 3-pass), online softmax, sinks.
// Q/K staged from pre-split planes; V split from g_qkv (transposed staging).
// Output written as bf16 hi/lo planes for the O-projection.
// ---------------------------------------------------------------------------
#define VSTR 36

__global__ __launch_bounds__(128)
void flash_attn(const float* __restrict__ sinks)
{
    __shared__ uint32_t Qs[2][64 * VSTR];
    __shared__ uint32_t Ks[2][64 * VSTR];
    __shared__ uint32_t Vs[2][64 * VSTR];

    const int h   = blockIdx.y;
    const int qt  = (S_ / 64 - 1) - blockIdx.x;   // heavy tiles first
    const int q0  = qt * 64;
    const int kv  = h >> 3;
    const int tid = threadIdx.x;
    const int wid = tid >> 5;
    const int lane = tid & 31;
    const int g   = lane >> 2;
    const int cq  = lane & 3;
    const float sink = sinks[h];

    // ---- stage Q tile from planes (plain word copies) ----
    {
        const int row = tid >> 1, e = tid & 1;
        const uint32_t* qh = (const uint32_t*)&g_qh[(size_t)(q0 + row) * (NH_ * HD_) + h * HD_ + e * 32];
        const uint32_t* ql = (const uint32_t*)&g_ql[(size_t)(q0 + row) * (NH_ * HD_) + h * HD_ + e * 32];
#pragma unroll
        for (int w = 0; w < 16; w++) {
            Qs[0][row * VSTR + e * 16 + w] = qh[w];
            Qs[1][row * VSTR + e * 16 + w] = ql[w];
        }
    }
    __syncthreads();

    // ---- Q fragments in registers ----
    uint32_t qa[2][4][4];
    {
        const int r0 = (wid * 16 + g) * VSTR;
        const int r8 = r0 + 8 * VSTR;
#pragma unroll
        for (int p = 0; p < 2; p++)
#pragma unroll
            for (int kt = 0; kt < 4; kt++) {
                const int w0 = kt * 8 + cq;
                qa[p][kt][0] = Qs[p][r0 + w0];
                qa[p][kt][1] = Qs[p][r8 + w0];
                qa[p][kt][2] = Qs[p][r0 + w0 + 4];
                qa[p][kt][3] = Qs[p][r8 + w0 + 4];
            }
    }

    float oacc[8][4];
#pragma unroll
    for (int nt = 0; nt < 8; nt++)
#pragma unroll
        for (int i = 0; i < 4; i++) oacc[nt][i] = 0.f;
    float m0 = -INFINITY, m8 = -INFINITY;
    float l0 = 0.f, l8 = 0.f;

    const int row_g  = q0 + wid * 16 + g;
    const int row_g8 = row_g + 8;
    const int ntiles = qt + 1;

    for (int t = 0; t < ntiles; t++) {
        const int k0 = t * 64;
        __syncthreads();

        // stage K tile from planes
        {
            const int key = tid >> 1, e = tid & 1;
            const uint32_t* kh = (const uint32_t*)&g_kh[(size_t)(k0 + key) * (NKV_ * HD_) + kv * HD_ + e * 32];
            const uint32_t* kl = (const uint32_t*)&g_kl[(size_t)(k0 + key) * (NKV_ * HD_) + kv * HD_ + e * 32];
#pragma unroll
            for (int w = 0; w < 16; w++) {
                Ks[0][key * VSTR + e * 16 + w] = kh[w];
                Ks[1][key * VSTR + e * 16 + w] = kl[w];
            }
        }
        // stage V transposed: Vs[dim][key-pair word] (split from fp32 g_qkv)
        {
            const int j = lane;
#pragma unroll
            for (int i = 0; i < 4; i++) {
                const int d = wid * 16 + i * 4;
                const float* v0 = &g_qkv[(size_t)(k0 + 2 * j) * QKV_N_ + VOFF_ + kv * HD_ + d];
                const float* v1 = v0 + QKV_N_;
                float4 a = *(const float4*)v0;
                float4 b = *(const float4*)v1;
                uint32_t hw, lw;
                split2(a.x, b.x, hw, lw); Vs[0][(d + 0) * VSTR + j] = hw; Vs[1][(d + 0) * VSTR + j] = lw;
                split2(a.y, b.y, hw, lw); Vs[0][(d + 1) * VSTR + j] = hw; Vs[1][(d + 1) * VSTR + j] = lw;
                split2(a.z, b.z, hw, lw); Vs[0][(d + 2) * VSTR + j] = hw; Vs[1][(d + 2) * VSTR + j] = lw;
                split2(a.w, b.w, hw, lw); Vs[0][(d + 3) * VSTR + j] = hw; Vs[1][(d + 3) * VSTR + j] = lw;
            }
        }
        __syncthreads();

        // ---- S = Q K^T ----
        float sacc[8][4];
#pragma unroll
        for (int nt = 0; nt < 8; nt++)
#pragma unroll
            for (int i = 0; i < 4; i++) sacc[nt][i] = 0.f;

#pragma unroll
        for (int kt = 0; kt < 4; kt++) {
#pragma unroll
            for (int nt = 0; nt < 8; nt++) {
                const int r0 = (nt * 8 + g) * VSTR + kt * 8 + cq;
                uint32_t bhf[2], blf[2];
                bhf[0] = Ks[0][r0]; bhf[1] = Ks[0][r0 + 4];
                blf[0] = Ks[1][r0]; blf[1] = Ks[1][r0 + 4];
                mma16816(sacc[nt], qa[0][kt], bhf);
                mma16816(sacc[nt], qa[0][kt], blf);
                mma16816(sacc[nt], qa[1][kt], bhf);
            }
        }

        // ---- scale + causal mask (last tile only) ----
        const bool last = (t == ntiles - 1);
#pragma unroll
        for (int nt = 0; nt < 8; nt++) {
            const int c0 = k0 + nt * 8 + 2 * cq;
#pragma unroll
            for (int i = 0; i < 4; i++) sacc[nt][i] *= SCALE_;
            if (last) {
                if (c0     > row_g)  sacc[nt][0] = -INFINITY;
                if (c0 + 1 > row_g)  sacc[nt][1] = -INFINITY;
                if (c0     > row_g8) sacc[nt][2] = -INFINITY;
                if (c0 + 1 > row_g8) sacc[nt][3] = -INFINITY;
            }
        }

        // ---- online softmax update ----
        float tm0 = -INFINITY, tm8 = -INFINITY;
#pragma unroll
        for (int nt = 0; nt < 8; nt++) {
            tm0 = fmaxf(tm0, fmaxf(sacc[nt][0], sacc[nt][1]));
            tm8 = fmaxf(tm8, fmaxf(sacc[nt][2], sacc[nt][3]));
        }
        tm0 = fmaxf(tm0, __shfl_xor_sync(0xffffffffu, tm0, 1));
        tm0 = fmaxf(tm0, __shfl_xor_sync(0xffffffffu, tm0, 2));
        tm8 = fmaxf(tm8, __shfl_xor_sync(0xffffffffu, tm8, 1));
        tm8 = fmaxf(tm8, __shfl_xor_sync(0xffffffffu, tm8, 2));

        const float m0n = fmaxf(m0, tm0);
        const float m8n = fmaxf(m8, tm8);
        const float a0 = __expf(m0 - m0n);
        const float a8 = __expf(m8 - m8n);
        m0 = m0n; m8 = m8n;
        l0 *= a0; l8 *= a8;
#pragma unroll
        for (int nt = 0; nt < 8; nt++) {
            oacc[nt][0] *= a0; oacc[nt][1] *= a0;
            oacc[nt][2] *= a8; oacc[nt][3] *= a8;
        }

#pragma unroll
        for (int nt = 0; nt < 8; nt++) {
            float p0 = (sacc[nt][0] == -INFINITY) ? 0.f : __expf(sacc[nt][0] - m0);
            float p1 = (sacc[nt][1] == -INFINITY) ? 0.f : __expf(sacc[nt][1] - m0);
            float p2 = (sacc[nt][2] == -INFINITY) ? 0.f : __expf(sacc[nt][2] - m8);
            float p3 = (sacc[nt][3] == -INFINITY) ? 0.f : __expf(sacc[nt][3] - m8);
            sacc[nt][0] = p0; sacc[nt][1] = p1; sacc[nt][2] = p2; sacc[nt][3] = p3;
            l0 += p0 + p1;
            l8 += p2 + p3;
        }

        // ---- O += P V ----
#pragma unroll
        for (int kt = 0; kt < 4; kt++) {
            uint32_t pah[4], pal[4];
            split2(sacc[2 * kt][0],     sacc[2 * kt][1],     pah[0], pal[0]);
            split2(sacc[2 * kt][2],     sacc[2 * kt][3],     pah[1], pal[1]);
            split2(sacc[2 * kt + 1][0], sacc[2 * kt + 1][1], pah[2], pal[2]);
            split2(sacc[2 * kt + 1][2], sacc[2 * kt + 1][3], pah[3], pal[3]);
#pragma unroll
            for (int nt = 0; nt < 8; nt++) {
                const int r0 = (nt * 8 + g) * VSTR + kt * 8 + cq;
                uint32_t vhf[2], vlf[2];
                vhf[0] = Vs[0][r0]; vhf[1] = Vs[0][r0 + 4];
                vlf[0] = Vs[1][r0]; vlf[1] = Vs[1][r0 + 4];
                mma16816(oacc[nt], pah, vhf);
                mma16816(oacc[nt], pah, vlf);
                mma16816(oacc[nt], pal, vhf);
            }
        }
    }

    // ---- finalize with sink; write bf16 hi/lo planes ----
    {
        const float m0n = fmaxf(m0, sink);
        const float m8n = fmaxf(m8, sink);
        const float a0 = __expf(m0 - m0n);
        const float a8 = __expf(m8 - m8n);
        l0 *= a0; l8 *= a8;
        l0 += __shfl_xor_sync(0xffffffffu, l0, 1);
        l0 += __shfl_xor_sync(0xffffffffu, l0, 2);
        l8 += __shfl_xor_sync(0xffffffffu, l8, 1);
        l8 += __shfl_xor_sync(0xffffffffu, l8, 2);
        const float inv0 = a0 / (l0 + __expf(sink - m0n));
        const float inv8 = a8 / (l8 + __expf(sink - m8n));
#pragma unroll
        for (int nt = 0; nt < 8; nt++) {
            const int col = h * HD_ + nt * 8 + 2 * cq;
            uint32_t hw, lw;
            split2(oacc[nt][0] * inv0, oacc[nt][1] * inv0, hw, lw);
            *(uint32_t*)&g_ah[(size_t)row_g * ATTN_N_ + col] = hw;
            *(uint32_t*)&g_al[(size_t)row_g * ATTN_N_ + col] = lw;
            split2(oacc[nt][2] * inv8, oacc[nt][3] * inv8, hw, lw);
            *(uint32_t*)&g_ah[(size_t)row_g8 * ATTN_N_ + col] = hw;
            *(uint32_t*)&g_al[(size_t)row_g8 * ATTN_N_ + col] = lw;
        }
    }
}

// ---------------------------------------------------------------------------
// Launch
// ---------------------------------------------------------------------------
extern "C" void kernel_launch(void* const* d_in, const int* in_sizes, int n_in,
                              void* d_out, int out_size)
{
    const int*   positions = (const int*)d_in[0];
    const float* hidden    = (const float*)d_in[1];
    const float* qkv_w     = (const float*)d_in[2];
    const float* o_w       = (const float*)d_in[3];
    const float* sinks     = (const float*)d_in[4];
    float*       out       = (float*)d_out;

    static bool attr_done = false;
    if (!attr_done) {
        cudaFuncSetAttribute(gemm_planes, cudaFuncAttributeMaxDynamicSharedMemorySize,
                             2 * BUF_ELEMS * (int)sizeof(__nv_bfloat16));
        attr_done = true;
    }

    void *p;
    cudaGetSymbolAddress(&p, g_qkv);  float* qkv = (float*)p;
    cudaGetSymbolAddress(&p, g_wqh);  __nv_bfloat16* wqh = (__nv_bfloat16*)p;
    cudaGetSymbolAddress(&p, g_wql);  __nv_bfloat16* wql = (__nv_bfloat16*)p;
    cudaGetSymbolAddress(&p, g_woh);  __nv_bfloat16* woh = (__nv_bfloat16*)p;
    cudaGetSymbolAddress(&p, g_wol);  __nv_bfloat16* wol = (__nv_bfloat16*)p;
    cudaGetSymbolAddress(&p, g_xh);   __nv_bfloat16* xh  = (__nv_bfloat16*)p;
    cudaGetSymbolAddress(&p, g_xl);   __nv_bfloat16* xl  = (__nv_bfloat16*)p;
    cudaGetSymbolAddress(&p, g_ah);   __nv_bfloat16* ah  = (__nv_bfloat16*)p;
    cudaGetSymbolAddress(&p, g_al);   __nv_bfloat16* al  = (__nv_bfloat16*)p;

    const int smem = 2 * BUF_ELEMS * (int)sizeof(__nv_bfloat16);

    // 0) pre-split weights + activations to bf16 planes
    split_f32<<<(QKV_N_ * H_) / 1024, 256>>>(qkv_w, wqh, wql, QKV_N_ * H_);
    split_f32<<<(H_ * ATTN_N_) / 1024, 256>>>(o_w, woh, wol, H_ * ATTN_N_);
    split_f32<<<(S_ * H_) / 1024, 256>>>(hidden, xh, xl, S_ * H_);

    // 1) QKV projection: [1024,2880] @ [5120,2880]^T -> g_qkv fp32
    gemm_planes<<<dim3(QKV_N_ / BN, S_ / BM), 256, smem>>>(xh, xl, wqh, wql, qkv, S_, QKV_N_, H_);

    // 2) RoPE + split Q/K to planes
    rope_split<<<S_ * (NH_ + NKV_), 32>>>(positions);

    // 3) Flash attention -> attn planes
    flash_attn<<<dim3(S_ / 64, NH_), 128>>>(sinks);

    // 4) O projection: attn planes @ o_w planes -> out fp32
    gemm_planes<<<dim3(H_ / BN, S_ / BM), 256, smem>>>(ah, al, woh, wol, out, S_, H_, ATTN_N_);
}